// round 3
// baseline (speedup 1.0000x reference)
#include <cuda_runtime.h>
#include <cuda_bf16.h>

// ---------------------------------------------------------------------------
// LMMD loss, GB300.  n = 8192 rows of D=256.  Upper-triangle tiled pass:
//   loss = sum_{p<=q} f * W(p,q) * Ksum(p,q),  Ksum = E+E^2+E^4+E^8+E^16,
//   E = exp(-l2/(16*bw)),  l2 = max(sq_p+sq_q-2*dot,0)
// Weights: SS -> class-equality lookup; ST -> single gather; TT -> rank-31 GEMM.
// bw via closed form: sum(l2) = 2n*S1 - 2*||colsum||^2.
// ---------------------------------------------------------------------------

#define TPD 32      // tiles per domain (4096/128)
#define NT  64      // tiles per side (8192/128)
#define TS  128     // tile size
#define BK  16

__device__ float g_sq[8192];
__device__ float g_sw[4096];
__device__ int   g_cls[4096];
__device__ float g_tv[4096*32];     // masked/normalized t_label, col 31 = 0 pad
__device__ float g_colsum[256];
__device__ float g_scalars[4];      // [0]=neg_r = -log2e/(16*bw), [1]=1/n_idx
__device__ float g_partials[NT*NT];

// ---------------------------------------------------------------------------
__global__ void k_zero() {
  int t = threadIdx.x;
  if (t < 256) g_colsum[t] = 0.f;
}

// ---------------------------------------------------------------------------
// Label statistics: s_cnt, t_cnt (col sums), argmax presence, mask, n_idx,
// per-row sw[] and tv[][] scratch.  Single block, 1024 threads.
__global__ void k_stats(const void* __restrict__ s_label_raw,
                        const float* __restrict__ t_label) {
  __shared__ float s_cnt[31], t_cnt[31], am_cnt[31];
  __shared__ float sw_c[32], tvd[32];
  __shared__ int use64;
  int tid = threadIdx.x;
  if (tid < 31) { s_cnt[tid] = 0.f; t_cnt[tid] = 0.f; am_cnt[tid] = 0.f; }
  if (tid == 0) use64 = 1;
  __syncthreads();

  // Detect int64 vs int32 label storage: int64 labels in [0,31) have all odd
  // 32-bit words == 0; int32 labels almost surely have a nonzero odd word.
  const int* l32 = (const int*)s_label_raw;
  for (int k = tid; k < 2048; k += 1024)
    if (l32[2*k + 1] != 0) use64 = 0;
  __syncthreads();
  bool u64 = (use64 != 0);
  const long long* l64 = (const long long*)s_label_raw;

  for (int i = tid; i < 4096; i += 1024) {
    int c = u64 ? (int)l64[i] : l32[i];
    atomicAdd(&s_cnt[c], 1.f);
  }

  float tc[31];
  #pragma unroll
  for (int c = 0; c < 31; c++) tc[c] = 0.f;
  for (int i = tid; i < 4096; i += 1024) {
    const float* row = t_label + i*31;
    float m = row[0]; int am = 0;
    #pragma unroll
    for (int c = 0; c < 31; c++) {
      float v = row[c];
      tc[c] += v;
      if (v > m) { m = v; am = c; }     // first-max (jnp.argmax semantics)
    }
    atomicAdd(&am_cnt[am], 1.f);
  }
  #pragma unroll
  for (int c = 0; c < 31; c++) {
    float v = tc[c];
    #pragma unroll
    for (int o = 16; o > 0; o >>= 1) v += __shfl_down_sync(0xffffffffu, v, o);
    if ((tid & 31) == 0) atomicAdd(&t_cnt[c], v);
  }
  __syncthreads();

  if (tid == 0) {
    float nidx = 0.f;
    for (int c = 0; c < 31; c++) {
      float msk = (s_cnt[c] > 0.f && am_cnt[c] > 0.f) ? 1.f : 0.f;
      nidx += msk;
      float sd = (s_cnt[c] == 0.f) ? 100.f : s_cnt[c];
      float td = (t_cnt[c] == 0.f) ? 100.f : t_cnt[c];
      sw_c[c] = msk / sd;
      tvd[c]  = msk / td;
    }
    sw_c[31] = 0.f; tvd[31] = 0.f;
    g_scalars[1] = 1.f / fmaxf(nidx, 1.f);
  }
  __syncthreads();

  for (int i = tid; i < 4096; i += 1024) {
    int c = u64 ? (int)l64[i] : l32[i];
    g_cls[i] = c;
    g_sw[i]  = sw_c[c];
  }
  for (int idx = tid; idx < 4096*32; idx += 1024) {
    int i = idx >> 5, c = idx & 31;
    g_tv[idx] = (c < 31) ? t_label[i*31 + c] * tvd[c] : 0.f;
  }
}

// ---------------------------------------------------------------------------
// Row squared norms: one warp per row.
__global__ void k_sq(const float* __restrict__ src, const float* __restrict__ tgt) {
  int row  = blockIdx.x * 8 + (threadIdx.x >> 5);
  int lane = threadIdx.x & 31;
  const float* r = (row < 4096) ? src + row*256 : tgt + (row - 4096)*256;
  float s = 0.f;
  #pragma unroll
  for (int k = 0; k < 8; k++) { float v = r[lane + 32*k]; s = fmaf(v, v, s); }
  #pragma unroll
  for (int o = 16; o > 0; o >>= 1) s += __shfl_down_sync(0xffffffffu, s, o);
  if (lane == 0) g_sq[row] = s;
}

// Column sums (for closed-form sum(l2)).
__global__ void k_colsum(const float* __restrict__ src, const float* __restrict__ tgt) {
  int d  = threadIdx.x;
  int r0 = blockIdx.x * 256;
  float s = 0.f;
  for (int r = r0; r < r0 + 256; r++) {
    const float* row = (r < 4096) ? src + r*256 : tgt + (r - 4096)*256;
    s += row[d];
  }
  atomicAdd(&g_colsum[d], s);
}

// bw + exp scale.
__global__ void k_bw() {
  __shared__ double sd[256];
  int tid = threadIdx.x;
  double s = 0.0;
  for (int i = tid; i < 8192; i += 256) s += (double)g_sq[i];
  sd[tid] = s; __syncthreads();
  for (int o = 128; o > 0; o >>= 1) { if (tid < o) sd[tid] += sd[tid + o]; __syncthreads(); }
  double S1 = sd[0];
  __syncthreads();
  double c = (double)g_colsum[tid];
  sd[tid] = c * c; __syncthreads();
  for (int o = 128; o > 0; o >>= 1) { if (tid < o) sd[tid] += sd[tid + o]; __syncthreads(); }
  if (tid == 0) {
    double n = 8192.0;
    double suml2 = 2.0*n*S1 - 2.0*sd[0];
    double bw = suml2 / (n*n - n);
    bw = fmax(bw, 1e-6) / 4.0;                         // / KERNEL_MUL^(5//2)
    g_scalars[0] = (float)(-1.4426950408889634 / (16.0 * bw));
  }
}

// ---------------------------------------------------------------------------
// FMA-pipe exp2 (keeps MUFU out of the critical path).  x <= 0.
__device__ __forceinline__ float fexp2(float x) {
  x = fmaxf(x, -40.f);
  float k = floorf(x + 0.5f);
  float r = x - k;                       // r in [-0.5, 0.5]
  float w = r * 0.69314718056f;          // |w| <= 0.347
  float p =            1.9841270e-4f;    // 1/7!
  p = fmaf(p, w, 1.3888889e-3f);         // 1/6!
  p = fmaf(p, w, 8.3333333e-3f);
  p = fmaf(p, w, 4.1666667e-2f);
  p = fmaf(p, w, 1.6666667e-1f);
  p = fmaf(p, w, 0.5f);
  p = fmaf(p, w, 1.0f);
  p = fmaf(p, w, 1.0f);
  return __int_as_float(__float_as_int(p) + (((int)k) << 23));
}

union SmemU {
  struct { float As[BK][TS]; float Bs[BK][TS]; } mm;   // 16 KB mainloop tiles
  struct { float tP[32][TS]; float tQ[32][TS]; } tv;   // 32 KB epilogue tv (transposed)
};

// Main tiled pass over upper-triangle 128x128 tiles.
__global__ void __launch_bounds__(256, 1)
k_main(const float* __restrict__ src, const float* __restrict__ tgt) {
  int bj = blockIdx.x, bi = blockIdx.y;
  int bIdx = bi * NT + bj;
  if (bi > bj) { if (threadIdx.x == 0) g_partials[bIdx] = 0.f; return; }

  __shared__ SmemU u;
  __shared__ float sqP[TS], sqQ[TS], swP[TS], swQ[TS];
  __shared__ int   cP[TS], cQ[TS];
  __shared__ float redbuf[8];

  int tid = threadIdx.x;
  bool pS = (bi < TPD), qS = (bj < TPD);
  const float* pBase = pS ? (src + bi*TS*256) : (tgt + (bi - TPD)*TS*256);
  const float* qBase = qS ? (src + bj*TS*256) : (tgt + (bj - TPD)*TS*256);

  int tx = tid & 15, ty = tid >> 4;     // 16x16 threads, 8x8 micro-tile each
  float acc[8][8];
  #pragma unroll
  for (int i = 0; i < 8; i++)
    #pragma unroll
    for (int j = 0; j < 8; j++) acc[i][j] = 0.f;

  int lrow = tid >> 2, lseg = tid & 3;

  for (int kb = 0; kb < 256; kb += BK) {
    float4 a0 = *(const float4*)(pBase + lrow      *256 + kb + lseg*4);
    float4 a1 = *(const float4*)(pBase + (lrow+64) *256 + kb + lseg*4);
    float4 b0 = *(const float4*)(qBase + lrow      *256 + kb + lseg*4);
    float4 b1 = *(const float4*)(qBase + (lrow+64) *256 + kb + lseg*4);
    __syncthreads();
    u.mm.As[lseg*4+0][lrow]    = a0.x; u.mm.As[lseg*4+1][lrow]    = a0.y;
    u.mm.As[lseg*4+2][lrow]    = a0.z; u.mm.As[lseg*4+3][lrow]    = a0.w;
    u.mm.As[lseg*4+0][lrow+64] = a1.x; u.mm.As[lseg*4+1][lrow+64] = a1.y;
    u.mm.As[lseg*4+2][lrow+64] = a1.z; u.mm.As[lseg*4+3][lrow+64] = a1.w;
    u.mm.Bs[lseg*4+0][lrow]    = b0.x; u.mm.Bs[lseg*4+1][lrow]    = b0.y;
    u.mm.Bs[lseg*4+2][lrow]    = b0.z; u.mm.Bs[lseg*4+3][lrow]    = b0.w;
    u.mm.Bs[lseg*4+0][lrow+64] = b1.x; u.mm.Bs[lseg*4+1][lrow+64] = b1.y;
    u.mm.Bs[lseg*4+2][lrow+64] = b1.z; u.mm.Bs[lseg*4+3][lrow+64] = b1.w;
    __syncthreads();
    #pragma unroll
    for (int k = 0; k < BK; k++) {
      float a[8], b[8];
      *(float4*)&a[0] = *(const float4*)&u.mm.As[k][ty*8];
      *(float4*)&a[4] = *(const float4*)&u.mm.As[k][ty*8 + 4];
      *(float4*)&b[0] = *(const float4*)&u.mm.Bs[k][tx*8];
      *(float4*)&b[4] = *(const float4*)&u.mm.Bs[k][tx*8 + 4];
      #pragma unroll
      for (int i = 0; i < 8; i++)
        #pragma unroll
        for (int j = 0; j < 8; j++) acc[i][j] = fmaf(a[i], b[j], acc[i][j]);
    }
  }
  __syncthreads();   // protect union switch

  int p0 = bi*TS, q0 = bj*TS;
  for (int r = tid; r < TS; r += 256) { sqP[r] = g_sq[p0 + r]; sqQ[r] = g_sq[q0 + r]; }
  if (pS) { for (int r = tid; r < TS; r += 256) { cP[r] = g_cls[p0+r]; swP[r] = g_sw[p0+r]; } }
  else    { for (int idx = tid; idx < TS*32; idx += 256) {
              int r = idx >> 5, c = idx & 31;
              u.tv.tP[c][r] = g_tv[(p0 - 4096)*32 + idx]; } }
  if (qS) { for (int r = tid; r < TS; r += 256) { cQ[r] = g_cls[q0+r]; swQ[r] = g_sw[q0+r]; } }
  else    { for (int idx = tid; idx < TS*32; idx += 256) {
              int r = idx >> 5, c = idx & 31;
              u.tv.tQ[c][r] = g_tv[(q0 - 4096)*32 + idx]; } }
  __syncthreads();

  int type = pS ? (qS ? 0 : 1) : 2;   // 0=SS, 1=ST, 2=TT

  // TT weight: rank-32 mini-GEMM  W = TvP * TvQ^T  (same access pattern as mainloop)
  float wacc[8][8];
  if (type == 2) {
    #pragma unroll
    for (int i = 0; i < 8; i++)
      #pragma unroll
      for (int j = 0; j < 8; j++) wacc[i][j] = 0.f;
    #pragma unroll
    for (int k = 0; k < 32; k++) {
      float a[8], b[8];
      *(float4*)&a[0] = *(const float4*)&u.tv.tP[k][ty*8];
      *(float4*)&a[4] = *(const float4*)&u.tv.tP[k][ty*8 + 4];
      *(float4*)&b[0] = *(const float4*)&u.tv.tQ[k][tx*8];
      *(float4*)&b[4] = *(const float4*)&u.tv.tQ[k][tx*8 + 4];
      #pragma unroll
      for (int i = 0; i < 8; i++)
        #pragma unroll
        for (int j = 0; j < 8; j++) wacc[i][j] = fmaf(a[i], b[j], wacc[i][j]);
    }
  }

  float neg_r = g_scalars[0];
  bool diag = (bi == bj);
  float local = 0.f;
  #pragma unroll
  for (int i = 0; i < 8; i++) {
    int p = ty*8 + i;
    float sqp = sqP[p];
    float swp = 0.f; int cp = 0;
    if (type != 2) { swp = swP[p]; cp = cP[p]; }
    #pragma unroll
    for (int j = 0; j < 8; j++) {
      int q = tx*8 + j;
      float w;
      if      (type == 0) w = (cp == cQ[q]) ? swp * swQ[q] : 0.f;
      else if (type == 1) w = -swp * u.tv.tQ[cp][q];
      else                w = wacc[i][j];
      float f = 2.f;
      if (diag) f = (p > q) ? 0.f : ((p == q) ? 1.f : 2.f);
      float l2 = fmaxf(fmaf(-2.f, acc[i][j], sqp + sqQ[q]), 0.f);
      float E  = fexp2(l2 * neg_r);          // exp(-l2/(16 bw))
      float E2 = E*E, E4 = E2*E2, E8 = E4*E4, E16 = E8*E8;
      local += (f * w) * (((E + E2) + (E4 + E8)) + E16);
    }
  }

  #pragma unroll
  for (int o = 16; o > 0; o >>= 1) local += __shfl_down_sync(0xffffffffu, local, o);
  if ((tid & 31) == 0) redbuf[tid >> 5] = local;
  __syncthreads();
  if (tid == 0) {
    float s = 0.f;
    #pragma unroll
    for (int wq = 0; wq < 8; wq++) s += redbuf[wq];
    g_partials[bIdx] = s;
  }
}

// ---------------------------------------------------------------------------
__global__ void k_final(float* __restrict__ out) {
  __shared__ double sd[256];
  int tid = threadIdx.x;
  double s = 0.0;
  for (int i = tid; i < NT*NT; i += 256) s += (double)g_partials[i];
  sd[tid] = s; __syncthreads();
  for (int o = 128; o > 0; o >>= 1) { if (tid < o) sd[tid] += sd[tid + o]; __syncthreads(); }
  if (tid == 0) out[0] = (float)(sd[0] * (double)g_scalars[1]);
}

// ---------------------------------------------------------------------------
extern "C" void kernel_launch(void* const* d_in, const int* in_sizes, int n_in,
                              void* d_out, int out_size) {
  const float* src  = (const float*)d_in[0];
  const float* tgt  = (const float*)d_in[1];
  const void*  slab = d_in[2];
  const float* tlab = (const float*)d_in[3];

  k_zero  <<<1, 256>>>();
  k_stats <<<1, 1024>>>(slab, tlab);
  k_sq    <<<1024, 256>>>(src, tgt);
  k_colsum<<<32, 256>>>(src, tgt);
  k_bw    <<<1, 256>>>();
  dim3 g(NT, NT);
  k_main  <<<g, 256>>>(src, tgt);
  k_final <<<1, 256>>>((float*)d_out);
}

// round 6
// speedup vs baseline: 2.4639x; 2.4639x over previous
#include <cuda_runtime.h>
#include <cstdint>

// ---------------------------------------------------------------------------
// LMMD loss, GB300.  tcgen05 unavailable (virtual arch compute_103 lacks the
// '-a' features), so the Gram matrix uses classic mma.sync.m16n8k8 tf32 with
// ldmatrix fragment loads and cp.async double buffering.  Inputs pre-rounded
// to tf32 (cvt.rna).  Epilogue fused from register accumulators; TT weights
// via exact-fp32 register mini-GEMM.
// ---------------------------------------------------------------------------

#define TPD 32
#define NT  64
#define TS  128
#define KC  16            // K-chunk (floats) per cp.async stage

__device__ __align__(16) float g_x[8192*256];   // tf32-rounded inputs
__device__ float g_sq[8192];
__device__ float g_sw[4096];
__device__ int   g_cls[4096];
__device__ float g_tv[4096*32];
__device__ float g_colsum[256];
__device__ float g_cnt_s[31], g_cnt_t[31], g_cnt_am[31];
__device__ float g_swc[32], g_tvd[32];
__device__ float g_scalars[4];      // [0]=neg_r, [1]=1/n_idx
__device__ int   g_use64;
__device__ float g_partials[NT*NT];

static __device__ __forceinline__ uint32_t smem_u32(const void* p) {
  uint32_t a;
  asm("{ .reg .u64 t; cvta.to.shared.u64 t, %1; cvt.u32.u64 %0, t; }"
      : "=r"(a) : "l"(p));
  return a;
}

// ---------------------------------------------------------------------------
// Prologue kernels
// ---------------------------------------------------------------------------
__global__ void k_pre0(const int* __restrict__ l32) {
  __shared__ int nz;
  int t = threadIdx.x;
  if (t == 0) nz = 0;
  if (t < 256) g_colsum[t] = 0.f;
  if (t < 31) { g_cnt_s[t] = 0.f; g_cnt_t[t] = 0.f; g_cnt_am[t] = 0.f; }
  __syncthreads();
  int bad = 0;
  for (int k = t; k < 2048; k += 256)
    if (l32[2*k + 1] != 0) bad = 1;
  if (bad) atomicOr(&nz, 1);
  __syncthreads();
  if (t == 0) g_use64 = nz ? 0 : 1;
}

// Round inputs to tf32 once (rna = round-to-nearest, unbiased).
__global__ void k_cvt(const float* __restrict__ s, const float* __restrict__ t) {
  int i = blockIdx.x * 256 + threadIdx.x;        // float4 index
  long base = (long)i * 4;
  const float* inp = (base < 1048576) ? (s + base) : (t + (base - 1048576));
  float4 v = *(const float4*)inp;
  uint32_t o0, o1, o2, o3;
  asm("cvt.rna.tf32.f32 %0, %1;" : "=r"(o0) : "f"(v.x));
  asm("cvt.rna.tf32.f32 %0, %1;" : "=r"(o1) : "f"(v.y));
  asm("cvt.rna.tf32.f32 %0, %1;" : "=r"(o2) : "f"(v.z));
  asm("cvt.rna.tf32.f32 %0, %1;" : "=r"(o3) : "f"(v.w));
  uint4 w = make_uint4(o0, o1, o2, o3);
  *(uint4*)&g_x[base] = w;
}

__global__ void k_stats1(const void* __restrict__ slab,
                         const float* __restrict__ t_label) {
  __shared__ float sh_s[31], sh_t[31], sh_a[31];
  int t = threadIdx.x, lane = t & 31;
  if (t < 31) { sh_s[t] = 0.f; sh_t[t] = 0.f; sh_a[t] = 0.f; }
  __syncthreads();
  int row = blockIdx.x * 128 + t;
  bool u64 = (g_use64 != 0);
  int c = u64 ? (int)((const long long*)slab)[row] : ((const int*)slab)[row];
  atomicAdd(&sh_s[c], 1.f);
  const float* r = t_label + row * 31;
  float m = r[0]; int am = 0;
  #pragma unroll
  for (int cc = 0; cc < 31; cc++) {
    float v = r[cc];
    if (v > m) { m = v; am = cc; }
    float s = v;
    #pragma unroll
    for (int o = 16; o > 0; o >>= 1) s += __shfl_down_sync(0xffffffffu, s, o);
    if (lane == 0) atomicAdd(&sh_t[cc], s);
  }
  atomicAdd(&sh_a[am], 1.f);
  __syncthreads();
  if (t < 31) {
    atomicAdd(&g_cnt_s[t],  sh_s[t]);
    atomicAdd(&g_cnt_t[t],  sh_t[t]);
    atomicAdd(&g_cnt_am[t], sh_a[t]);
  }
}

__global__ void k_stats2() {
  int t = threadIdx.x;   // 32 threads
  float msk = 0.f, swc = 0.f, tvd = 0.f;
  if (t < 31) {
    float s = g_cnt_s[t], tc = g_cnt_t[t], a = g_cnt_am[t];
    msk = (s > 0.f && a > 0.f) ? 1.f : 0.f;
    swc = msk / ((s == 0.f) ? 100.f : s);
    tvd = msk / ((tc == 0.f) ? 100.f : tc);
  }
  g_swc[t] = swc; g_tvd[t] = tvd;
  float n = msk;
  #pragma unroll
  for (int o = 16; o > 0; o >>= 1) n += __shfl_down_sync(0xffffffffu, n, o);
  if (t == 0) g_scalars[1] = 1.f / fmaxf(n, 1.f);
}

__global__ void k_fill(const void* __restrict__ slab,
                       const float* __restrict__ t_label) {
  bool u64 = (g_use64 != 0);
  int stride = gridDim.x * blockDim.x;
  for (int i = blockIdx.x * blockDim.x + threadIdx.x; i < 4096; i += stride) {
    int c = u64 ? (int)((const long long*)slab)[i] : ((const int*)slab)[i];
    g_cls[i] = c;
    g_sw[i]  = g_swc[c];
  }
  for (int idx = blockIdx.x * blockDim.x + threadIdx.x; idx < 4096*32; idx += stride) {
    int i = idx >> 5, c = idx & 31;
    g_tv[idx] = (c < 31) ? t_label[i*31 + c] * g_tvd[c] : 0.f;
  }
}

__global__ void k_norm(const float* __restrict__ src, const float* __restrict__ tgt) {
  int b = blockIdx.x, t = threadIdx.x, warp = t >> 5, lane = t & 31;
  #pragma unroll
  for (int it = 0; it < 4; it++) {
    int row = b * 32 + it * 8 + warp;
    const float* r = (row < 4096) ? src + row*256 : tgt + (row - 4096)*256;
    float s = 0.f;
    #pragma unroll
    for (int k = 0; k < 8; k++) { float v = r[lane + 32*k]; s = fmaf(v, v, s); }
    #pragma unroll
    for (int o = 16; o > 0; o >>= 1) s += __shfl_down_sync(0xffffffffu, s, o);
    if (lane == 0) g_sq[row] = s;
  }
  float cs = 0.f;
  for (int rr = 0; rr < 32; rr++) {
    int row = b * 32 + rr;
    const float* r = (row < 4096) ? src + row*256 : tgt + (row - 4096)*256;
    cs += r[t];
  }
  atomicAdd(&g_colsum[t], cs);
}

__global__ void k_bw() {
  __shared__ double sd[256];
  int tid = threadIdx.x;
  double s = 0.0;
  for (int i = tid; i < 8192; i += 256) s += (double)g_sq[i];
  sd[tid] = s; __syncthreads();
  for (int o = 128; o > 0; o >>= 1) { if (tid < o) sd[tid] += sd[tid + o]; __syncthreads(); }
  double S1 = sd[0];
  __syncthreads();
  double c = (double)g_colsum[tid];
  sd[tid] = c * c; __syncthreads();
  for (int o = 128; o > 0; o >>= 1) { if (tid < o) sd[tid] += sd[tid + o]; __syncthreads(); }
  if (tid == 0) {
    double n = 8192.0;
    double suml2 = 2.0*n*S1 - 2.0*sd[0];
    double bw = suml2 / (n*n - n);
    bw = fmax(bw, 1e-6) / 4.0;
    g_scalars[0] = (float)(-1.4426950408889634 / (16.0 * bw));
  }
}

// FMA-pipe exp2(x) for x <= 0.
__device__ __forceinline__ float fexp2(float x) {
  x = fmaxf(x, -60.f);
  float t = x + 12582912.f;                        // RN round-to-int trick
  int  ki = __float_as_int(t) - 0x4B400000;
  float r = x - (t - 12582912.f);                  // r in [-0.5, 0.5]
  float w = r * 0.69314718056f;
  float p =            1.9841270e-4f;
  p = fmaf(p, w, 1.3888889e-3f);
  p = fmaf(p, w, 8.3333333e-3f);
  p = fmaf(p, w, 4.1666667e-2f);
  p = fmaf(p, w, 1.6666667e-1f);
  p = fmaf(p, w, 0.5f);
  p = fmaf(p, w, 1.0f);
  p = fmaf(p, w, 1.0f);
  return __int_as_float(__float_as_int(p) + (ki << 23));
}

// ---------------------------------------------------------------------------
// Main tile kernel: warp-level tf32 mma.sync GEMM + fused epilogue
// ---------------------------------------------------------------------------
// SMEM granule layout per buffer: addr(row,g) = (row>>3)*512 + g*128 + (row&7)*16
// bytes, g = 16B granule (4 tf32) within the KC=16 chunk.  Every ldmatrix
// piece (8 rows x 16B, fixed g) is 128B contiguous -> conflict-free.

union SmemU {
  float mm[4][2048];     // [0]=As buf0, [1]=As buf1, [2]=Bs buf0, [3]=Bs buf1
  float tv[2][4224];     // tP[32][132], tQ[32][132]
};

#define LDMX4(r0,r1,r2,r3,addr)                                                \
  asm volatile("ldmatrix.sync.aligned.m8n8.x4.shared.b16 {%0,%1,%2,%3}, [%4];" \
    : "=r"(r0), "=r"(r1), "=r"(r2), "=r"(r3) : "r"(addr))

#define MMA_TF32(c, a, b)                                                      \
  asm volatile("mma.sync.aligned.m16n8k8.row.col.f32.tf32.tf32.f32 "           \
    "{%0,%1,%2,%3}, {%4,%5,%6,%7}, {%8,%9}, {%0,%1,%2,%3};"                    \
    : "+f"((c)[0]), "+f"((c)[1]), "+f"((c)[2]), "+f"((c)[3])                   \
    : "r"((a)[0]), "r"((a)[1]), "r"((a)[2]), "r"((a)[3]),                      \
      "r"((b)[0]), "r"((b)[1]))

// cp.async one K-chunk (A + B tiles) into staging buffer.
static __device__ __forceinline__ void issue_chunk(
    const float* __restrict__ pBase, const float* __restrict__ qBase,
    uint32_t aDst, uint32_t bDst, int kb, int tid) {
  #pragma unroll
  for (int it = 0; it < 2; it++) {
    int gi  = tid * 2 + it;             // 0..511 granules
    int row = gi >> 2, g = gi & 3;
    const float* sA = pBase + row*256 + kb*KC + g*4;
    const float* sB = qBase + row*256 + kb*KC + g*4;
    uint32_t off = (uint32_t)((row >> 3)*512 + g*128 + (row & 7)*16);
    asm volatile("cp.async.cg.shared.global [%0], [%1], 16;"
                 :: "r"(aDst + off), "l"(sA) : "memory");
    asm volatile("cp.async.cg.shared.global [%0], [%1], 16;"
                 :: "r"(bDst + off), "l"(sB) : "memory");
  }
  asm volatile("cp.async.commit_group;" ::: "memory");
}

__global__ void __launch_bounds__(256, 2)
k_main() {
  int bj = blockIdx.x, bi = blockIdx.y;
  int bIdx = bi * NT + bj;
  if (bi > bj) { if (threadIdx.x == 0) g_partials[bIdx] = 0.f; return; }

  __shared__ __align__(16) SmemU u;
  __shared__ float sqP[TS], sqQ[TS], swP[TS], swQ[TS];
  __shared__ int   cP[TS], cQ[TS];
  __shared__ float redbuf[8];

  int tid  = threadIdx.x;
  int warp = tid >> 5, lane = tid & 31;
  int warpM = warp & 1, warpN = warp >> 1;    // 2 x 4 warp grid, 64x32 tiles

  const float* pBase = g_x + (long)bi * TS * 256;
  const float* qBase = g_x + (long)bj * TS * 256;

  uint32_t aS[2] = { smem_u32(&u.mm[0]), smem_u32(&u.mm[1]) };
  uint32_t bS[2] = { smem_u32(&u.mm[2]), smem_u32(&u.mm[3]) };

  float acc[16][4];
  #pragma unroll
  for (int i = 0; i < 16; i++)
    #pragma unroll
    for (int v = 0; v < 4; v++) acc[i][v] = 0.f;

  issue_chunk(pBase, qBase, aS[0], bS[0], 0, tid);
  for (int kb = 0; kb < 16; kb++) {
    if (kb < 15) {
      issue_chunk(pBase, qBase, aS[(kb+1)&1], bS[(kb+1)&1], kb+1, tid);
      asm volatile("cp.async.wait_group 1;" ::: "memory");
    } else {
      asm volatile("cp.async.wait_group 0;" ::: "memory");
    }
    __syncthreads();

    uint32_t aB = aS[kb & 1], bB = bS[kb & 1];
    int piece = lane >> 3, pr = lane & 7;
    #pragma unroll
    for (int ks = 0; ks < 2; ks++) {          // two K=8 steps per chunk
      uint32_t aF[4][4], bF[4][2];
      #pragma unroll
      for (int mi = 0; mi < 4; mi++) {
        uint32_t addr = aB + (uint32_t)(
            (warpM*8 + mi*2 + (piece & 1))*512 + (2*ks + (piece >> 1))*128 + pr*16);
        LDMX4(aF[mi][0], aF[mi][1], aF[mi][2], aF[mi][3], addr);
      }
      #pragma unroll
      for (int np = 0; np < 2; np++) {        // n-tile pairs
        int nt = np*2 + (piece >> 1);
        uint32_t addr = bB + (uint32_t)(
            (warpN*4 + nt)*512 + (2*ks + (piece & 1))*128 + pr*16);
        LDMX4(bF[np*2][0], bF[np*2][1], bF[np*2+1][0], bF[np*2+1][1], addr);
      }
      #pragma unroll
      for (int mi = 0; mi < 4; mi++)
        #pragma unroll
        for (int ni = 0; ni < 4; ni++)
          MMA_TF32(acc[mi*4 + ni], aF[mi], bF[ni]);
    }
    __syncthreads();
  }

  // ---- epilogue metadata + tv tiles (reuse SMEM) ----
  int p0 = bi*TS, q0 = bj*TS;
  bool pS = (bi < TPD), qS = (bj < TPD);
  int type = pS ? (qS ? 0 : 1) : 2;   // 0=SS 1=ST 2=TT
  for (int r = tid; r < TS; r += 256) { sqP[r] = g_sq[p0 + r]; sqQ[r] = g_sq[q0 + r]; }
  if (pS) {
    for (int r = tid; r < TS; r += 256) { cP[r] = g_cls[p0 + r]; swP[r] = g_sw[p0 + r]; }
  } else {
    for (int idx = tid; idx < 4096; idx += 256) {
      int r = idx >> 5, c = idx & 31;
      u.tv[0][c*132 + r] = g_tv[(p0 - 4096)*32 + idx];
    }
  }
  if (qS) {
    for (int r = tid; r < TS; r += 256) { cQ[r] = g_cls[q0 + r]; swQ[r] = g_sw[q0 + r]; }
  } else {
    for (int idx = tid; idx < 4096; idx += 256) {
      int r = idx >> 5, c = idx & 31;
      u.tv[1][c*132 + r] = g_tv[(q0 - 4096)*32 + idx];
    }
  }
  __syncthreads();

  float neg_r = g_scalars[0];
  bool diag = (bi == bj);
  float local = 0.f;

  // Per-thread element coordinates (C-fragment mapping):
  //   pi = mi*2+h : p = warpM*64 + mi*16 + h*8 + (lane>>2)
  //   qi = ni*2+j : q = warpN*32 + ni*8 + j + 2*(lane&3)
  int pv[8]; float sqp[8];
  int qv[8]; float sqq[8];
  #pragma unroll
  for (int pi = 0; pi < 8; pi++) {
    int p = warpM*64 + (pi >> 1)*16 + (pi & 1)*8 + (lane >> 2);
    pv[pi] = p; sqp[pi] = sqP[p];
  }
  #pragma unroll
  for (int qi = 0; qi < 8; qi++) {
    int q = warpN*32 + (qi >> 1)*8 + (qi & 1) + 2*(lane & 3);
    qv[qi] = q; sqq[qi] = sqQ[q];
  }

  #define CONTRIB(wv, dotv, pi, qi) do {                                       \
    float f_ = 2.f;                                                            \
    if (diag) { int p_ = pv[pi], q_ = qv[qi];                                  \
                f_ = (p_ > q_) ? 0.f : ((p_ == q_) ? 1.f : 2.f); }             \
    float l2_ = fmaxf(fmaf(-2.f, (dotv), sqp[pi] + sqq[qi]), 0.f);             \
    float E_  = fexp2(l2_ * neg_r);                                            \
    float E2_ = E_*E_, E4_ = E2_*E2_, E8_ = E4_*E4_, E16_ = E8_*E8_;           \
    local = fmaf(f_ * (wv), ((E_ + E2_) + (E4_ + E8_)) + E16_, local);         \
  } while (0)

  if (type == 0) {          // SS: class-equality lookup
    int cpA[8]; float swpA[8]; int cqA[8]; float swqA[8];
    #pragma unroll
    for (int pi = 0; pi < 8; pi++) { cpA[pi] = cP[pv[pi]]; swpA[pi] = swP[pv[pi]]; }
    #pragma unroll
    for (int qi = 0; qi < 8; qi++) { cqA[qi] = cQ[qv[qi]]; swqA[qi] = swQ[qv[qi]]; }
    #pragma unroll
    for (int mi = 0; mi < 4; mi++)
      #pragma unroll
      for (int ni = 0; ni < 4; ni++)
        #pragma unroll
        for (int v = 0; v < 4; v++) {
          int pi = mi*2 + (v >> 1), qi = ni*2 + (v & 1);
          float w = (cpA[pi] == cqA[qi]) ? swpA[pi]*swqA[qi] : 0.f;
          CONTRIB(w, acc[mi*4+ni][v], pi, qi);
        }
  } else if (type == 1) {   // ST: gather tvQ[class(p)][q]
    int cpA[8]; float swpA[8];
    #pragma unroll
    for (int pi = 0; pi < 8; pi++) { cpA[pi] = cP[pv[pi]]; swpA[pi] = swP[pv[pi]]; }
    #pragma unroll
    for (int mi = 0; mi < 4; mi++)
      #pragma unroll
      for (int ni = 0; ni < 4; ni++)
        #pragma unroll
        for (int v = 0; v < 4; v++) {
          int pi = mi*2 + (v >> 1), qi = ni*2 + (v & 1);
          float w = -swpA[pi] * u.tv[1][cpA[pi]*132 + qv[qi]];
          CONTRIB(w, acc[mi*4+ni][v], pi, qi);
        }
  } else {                  // TT: exact-fp32 register mini-GEMM, two q-halves
    #pragma unroll
    for (int qh = 0; qh < 2; qh++) {
      float W[8][4];
      #pragma unroll
      for (int pi = 0; pi < 8; pi++)
        #pragma unroll
        for (int qi = 0; qi < 4; qi++) W[pi][qi] = 0.f;
      for (int k = 0; k < 32; k++) {
        float a[8], b[4];
        #pragma unroll
        for (int pi = 0; pi < 8; pi++) a[pi] = u.tv[0][k*132 + pv[pi]];
        #pragma unroll
        for (int qi = 0; qi < 4; qi++) b[qi] = u.tv[1][k*132 + qv[qh*4 + qi]];
        #pragma unroll
        for (int pi = 0; pi < 8; pi++)
          #pragma unroll
          for (int qi = 0; qi < 4; qi++) W[pi][qi] = fmaf(a[pi], b[qi], W[pi][qi]);
      }
      #pragma unroll
      for (int ni = qh*2; ni < qh*2 + 2; ni++)
        #pragma unroll
        for (int mi = 0; mi < 4; mi++)
          #pragma unroll
          for (int v = 0; v < 4; v++) {
            int pi = mi*2 + (v >> 1), qi = ni*2 + (v & 1);
            CONTRIB(W[pi][qi - qh*4], acc[mi*4+ni][v], pi, qi);
          }
    }
  }

  #pragma unroll
  for (int o = 16; o > 0; o >>= 1) local += __shfl_down_sync(0xffffffffu, local, o);
  if (lane == 0) redbuf[warp] = local;
  __syncthreads();
  if (tid == 0) {
    float s = 0.f;
    #pragma unroll
    for (int wq = 0; wq < 8; wq++) s += redbuf[wq];
    g_partials[bIdx] = s;
  }
}

// ---------------------------------------------------------------------------
__global__ void k_final(float* __restrict__ out) {
  __shared__ double sd[256];
  int tid = threadIdx.x;
  double s = 0.0;
  for (int i = tid; i < NT*NT; i += 256) s += (double)g_partials[i];
  sd[tid] = s; __syncthreads();
  for (int o = 128; o > 0; o >>= 1) { if (tid < o) sd[tid] += sd[tid + o]; __syncthreads(); }
  if (tid == 0) out[0] = (float)(sd[0] * (double)g_scalars[1]);
}

// ---------------------------------------------------------------------------
extern "C" void kernel_launch(void* const* d_in, const int* in_sizes, int n_in,
                              void* d_out, int out_size) {
  const float* src  = (const float*)d_in[0];
  const float* tgt  = (const float*)d_in[1];
  const void*  slab = d_in[2];
  const float* tlab = (const float*)d_in[3];

  k_pre0  <<<1, 256>>>((const int*)slab);
  k_cvt   <<<2048, 256>>>(src, tgt);
  k_stats1<<<32, 128>>>(slab, tlab);
  k_stats2<<<1, 32>>>();
  k_fill  <<<128, 256>>>(slab, tlab);
  k_norm  <<<256, 256>>>(src, tgt);
  k_bw    <<<1, 256>>>();
  dim3 g(NT, NT);
  k_main  <<<g, 256>>>();
  k_final <<<1, 256>>>((float*)d_out);
}

// round 9
// speedup vs baseline: 2.6234x; 1.0647x over previous
#include <cuda_runtime.h>
#include <cstdint>

// ---------------------------------------------------------------------------
// LMMD loss, GB300.  Gram matrix via classic mma.sync.m16n8k8 tf32 (base PTX
// ISA; tcgen05 needs an '-a' virtual arch the harness doesn't use) with
// ldmatrix fragment loads and a 3-stage cp.async pipeline (1 sync per chunk).
// Inputs pre-rounded to tf32 (cvt.rna).  Fused epilogue from register
// accumulators; TT weights via exact-fp32 register mini-GEMM in n-quarters.
// 1D triangular grid: only the 2080 upper-triangle tiles launch.
// ---------------------------------------------------------------------------

#define TPD 32
#define NT  64
#define TS  128
#define KC  16            // K-chunk (floats) per cp.async stage
#define NTILES 2080       // NT*(NT+1)/2

__device__ __align__(16) float g_x[8192*256];   // tf32-rounded inputs
__device__ float g_sq[8192];
__device__ float g_sw[4096];
__device__ int   g_cls[4096];
__device__ float g_tv[4096*32];
__device__ float g_colsum[256];
__device__ float g_cnt_s[31], g_cnt_t[31], g_cnt_am[31];
__device__ float g_swc[32], g_tvd[32];
__device__ float g_scalars[4];      // [0]=neg_r, [1]=1/n_idx
__device__ int   g_use64;
__device__ int   g_ctr0, g_ctr1;    // last-block-done counters
__device__ float g_partials[NTILES];

static __device__ __forceinline__ uint32_t smem_u32(const void* p) {
  uint32_t a;
  asm("{ .reg .u64 t; cvta.to.shared.u64 t, %1; cvt.u32.u64 %0, t; }"
      : "=r"(a) : "l"(p));
  return a;
}

// ---------------------------------------------------------------------------
// Prologue kernels
// ---------------------------------------------------------------------------
__global__ void k_pre0(const int* __restrict__ l32) {
  __shared__ int nz;
  int t = threadIdx.x;
  if (t == 0) { nz = 0; g_ctr0 = 0; g_ctr1 = 0; }
  if (t < 256) g_colsum[t] = 0.f;
  if (t < 31) { g_cnt_s[t] = 0.f; g_cnt_t[t] = 0.f; g_cnt_am[t] = 0.f; }
  __syncthreads();
  int bad = 0;
  for (int k = t; k < 2048; k += 256)
    if (l32[2*k + 1] != 0) bad = 1;
  if (bad) atomicOr(&nz, 1);
  __syncthreads();
  if (t == 0) g_use64 = nz ? 0 : 1;
}

// Round inputs to tf32 once (rna = round-to-nearest, unbiased).
__global__ void k_cvt(const float* __restrict__ s, const float* __restrict__ t) {
  int i = blockIdx.x * 256 + threadIdx.x;        // float4 index
  long base = (long)i * 4;
  const float* inp = (base < 1048576) ? (s + base) : (t + (base - 1048576));
  float4 v = *(const float4*)inp;
  uint32_t o0, o1, o2, o3;
  asm("cvt.rna.tf32.f32 %0, %1;" : "=r"(o0) : "f"(v.x));
  asm("cvt.rna.tf32.f32 %0, %1;" : "=r"(o1) : "f"(v.y));
  asm("cvt.rna.tf32.f32 %0, %1;" : "=r"(o2) : "f"(v.z));
  asm("cvt.rna.tf32.f32 %0, %1;" : "=r"(o3) : "f"(v.w));
  uint4 w = make_uint4(o0, o1, o2, o3);
  *(uint4*)&g_x[base] = w;
}

// 32 blocks x 128 threads; the last block to finish also derives
// per-class weights + n_idx (former k_stats2).
__global__ void k_stats(const void* __restrict__ slab,
                        const float* __restrict__ t_label) {
  __shared__ float sh_s[31], sh_t[31], sh_a[31];
  __shared__ int isLast;
  int t = threadIdx.x, lane = t & 31;
  if (t < 31) { sh_s[t] = 0.f; sh_t[t] = 0.f; sh_a[t] = 0.f; }
  __syncthreads();
  int row = blockIdx.x * 128 + t;
  bool u64 = (g_use64 != 0);
  int c = u64 ? (int)((const long long*)slab)[row] : ((const int*)slab)[row];
  atomicAdd(&sh_s[c], 1.f);
  const float* r = t_label + row * 31;
  float m = r[0]; int am = 0;
  #pragma unroll
  for (int cc = 0; cc < 31; cc++) {
    float v = r[cc];
    if (v > m) { m = v; am = cc; }
    float s = v;
    #pragma unroll
    for (int o = 16; o > 0; o >>= 1) s += __shfl_down_sync(0xffffffffu, s, o);
    if (lane == 0) atomicAdd(&sh_t[cc], s);
  }
  atomicAdd(&sh_a[am], 1.f);
  __syncthreads();
  if (t < 31) {
    atomicAdd(&g_cnt_s[t],  sh_s[t]);
    atomicAdd(&g_cnt_t[t],  sh_t[t]);
    atomicAdd(&g_cnt_am[t], sh_a[t]);
  }
  if (t == 0) {
    __threadfence();
    int o = atomicAdd(&g_ctr0, 1);
    isLast = (o == 31);
  }
  __syncthreads();
  if (isLast && t < 32) {
    __threadfence();
    float msk = 0.f, swc = 0.f, tvd = 0.f;
    if (t < 31) {
      float s = g_cnt_s[t], tc = g_cnt_t[t], a = g_cnt_am[t];
      msk = (s > 0.f && a > 0.f) ? 1.f : 0.f;
      swc = msk / ((s == 0.f) ? 100.f : s);
      tvd = msk / ((tc == 0.f) ? 100.f : tc);
    }
    g_swc[t] = swc; g_tvd[t] = tvd;
    float n = msk;
    #pragma unroll
    for (int o = 16; o > 0; o >>= 1) n += __shfl_down_sync(0xffffffffu, n, o);
    if (t == 0) g_scalars[1] = 1.f / fmaxf(n, 1.f);
  }
}

__global__ void k_fill(const void* __restrict__ slab,
                       const float* __restrict__ t_label) {
  bool u64 = (g_use64 != 0);
  int stride = gridDim.x * blockDim.x;
  for (int i = blockIdx.x * blockDim.x + threadIdx.x; i < 4096; i += stride) {
    int c = u64 ? (int)((const long long*)slab)[i] : ((const int*)slab)[i];
    g_cls[i] = c;
    g_sw[i]  = g_swc[c];
  }
  for (int idx = blockIdx.x * blockDim.x + threadIdx.x; idx < 4096*32; idx += stride) {
    int i = idx >> 5, c = idx & 31;
    g_tv[idx] = (c < 31) ? t_label[i*31 + c] * g_tvd[c] : 0.f;
  }
}

// 256 blocks x 256 threads: sq norms + colsums; last block computes bw.
__global__ void k_norm(const float* __restrict__ src, const float* __restrict__ tgt) {
  __shared__ double sd[256];
  __shared__ int isLast;
  int b = blockIdx.x, t = threadIdx.x, warp = t >> 5, lane = t & 31;
  #pragma unroll
  for (int it = 0; it < 4; it++) {
    int row = b * 32 + it * 8 + warp;
    const float* r = (row < 4096) ? src + row*256 : tgt + (row - 4096)*256;
    float s = 0.f;
    #pragma unroll
    for (int k = 0; k < 8; k++) { float v = r[lane + 32*k]; s = fmaf(v, v, s); }
    #pragma unroll
    for (int o = 16; o > 0; o >>= 1) s += __shfl_down_sync(0xffffffffu, s, o);
    if (lane == 0) g_sq[row] = s;
  }
  float cs = 0.f;
  for (int rr = 0; rr < 32; rr++) {
    int row = b * 32 + rr;
    const float* r = (row < 4096) ? src + row*256 : tgt + (row - 4096)*256;
    cs += r[t];
  }
  atomicAdd(&g_colsum[t], cs);
  if (t == 0) {
    __threadfence();
    int o = atomicAdd(&g_ctr1, 1);
    isLast = (o == 255);
  }
  __syncthreads();
  if (!isLast) return;
  __threadfence();
  double s = 0.0;
  for (int i = t; i < 8192; i += 256) s += (double)g_sq[i];
  sd[t] = s; __syncthreads();
  for (int o = 128; o > 0; o >>= 1) { if (t < o) sd[t] += sd[t + o]; __syncthreads(); }
  double S1 = sd[0];
  __syncthreads();
  double c = (double)g_colsum[t];
  sd[t] = c * c; __syncthreads();
  for (int o = 128; o > 0; o >>= 1) { if (t < o) sd[t] += sd[t + o]; __syncthreads(); }
  if (t == 0) {
    double n = 8192.0;
    double suml2 = 2.0*n*S1 - 2.0*sd[0];
    double bw = suml2 / (n*n - n);
    bw = fmax(bw, 1e-6) / 4.0;
    g_scalars[0] = (float)(-1.4426950408889634 / (16.0 * bw));
  }
}

// FMA-pipe exp2(x) for x <= 0.
__device__ __forceinline__ float fexp2(float x) {
  x = fmaxf(x, -60.f);
  float t = x + 12582912.f;                        // RN round-to-int trick
  int  ki = __float_as_int(t) - 0x4B400000;
  float r = x - (t - 12582912.f);                  // r in [-0.5, 0.5]
  float w = r * 0.69314718056f;
  float p =            1.9841270e-4f;
  p = fmaf(p, w, 1.3888889e-3f);
  p = fmaf(p, w, 8.3333333e-3f);
  p = fmaf(p, w, 4.1666667e-2f);
  p = fmaf(p, w, 1.6666667e-1f);
  p = fmaf(p, w, 0.5f);
  p = fmaf(p, w, 1.0f);
  p = fmaf(p, w, 1.0f);
  return __int_as_float(__float_as_int(p) + (ki << 23));
}

// ---------------------------------------------------------------------------
// Main tile kernel: warp-level tf32 mma.sync GEMM, 3-stage pipeline,
// fused epilogue.  SMEM = one 48KB union (stage buffers | epilogue scratch).
// ---------------------------------------------------------------------------
// Stage buffer layout per A/B: addr(row,g) = (row>>3)*512 + g*128 + (row&7)*16
// bytes, g = 16B granule within the KC=16 chunk.  Conflict-free ldmatrix.

union SmemU {
  float mm[3][2][2048];     // [stage][0=A,1=B][8KB floats]  = 48KB exactly
  struct {
    float tv0[4224], tv1[4224];              // tv[32][132] each
    float sqP[TS], sqQ[TS], swP[TS], swQ[TS];
    float red[32];
    int   cP[TS], cQ[TS];
  } ep;                                       // ~37KB
};

#define LDMX4(r0,r1,r2,r3,addr)                                                \
  asm volatile("ldmatrix.sync.aligned.m8n8.x4.shared.b16 {%0,%1,%2,%3}, [%4];" \
    : "=r"(r0), "=r"(r1), "=r"(r2), "=r"(r3) : "r"(addr))

#define MMA_TF32(c, a, b)                                                      \
  asm volatile("mma.sync.aligned.m16n8k8.row.col.f32.tf32.tf32.f32 "           \
    "{%0,%1,%2,%3}, {%4,%5,%6,%7}, {%8,%9}, {%0,%1,%2,%3};"                    \
    : "+f"((c)[0]), "+f"((c)[1]), "+f"((c)[2]), "+f"((c)[3])                   \
    : "r"((a)[0]), "r"((a)[1]), "r"((a)[2]), "r"((a)[3]),                      \
      "r"((b)[0]), "r"((b)[1]))

static __device__ __forceinline__ void issue_chunk(
    const float* __restrict__ pBase, const float* __restrict__ qBase,
    uint32_t aDst, uint32_t bDst, int kb, int tid) {
  #pragma unroll
  for (int it = 0; it < 2; it++) {
    int gi  = tid * 2 + it;             // 0..511 granules
    int row = gi >> 2, g = gi & 3;
    const float* sA = pBase + row*256 + kb*KC + g*4;
    const float* sB = qBase + row*256 + kb*KC + g*4;
    uint32_t off = (uint32_t)((row >> 3)*512 + g*128 + (row & 7)*16);
    asm volatile("cp.async.cg.shared.global [%0], [%1], 16;"
                 :: "r"(aDst + off), "l"(sA) : "memory");
    asm volatile("cp.async.cg.shared.global [%0], [%1], 16;"
                 :: "r"(bDst + off), "l"(sB) : "memory");
  }
  asm volatile("cp.async.commit_group;" ::: "memory");
}

__global__ void __launch_bounds__(256, 2)
k_main() {
  // triangular decode: blockIdx.x -> (bi <= bj)
  int t0 = blockIdx.x;
  int bi = (int)(64.5f - sqrtf(4160.25f - 2.f*(float)t0));
  while ((bi+1)*64 - ((bi+1)*bi)/2 <= t0) bi++;
  while (bi*64 - (bi*(bi-1))/2 > t0) bi--;
  int bj = bi + (t0 - (bi*64 - (bi*(bi-1))/2));

  __shared__ __align__(16) SmemU u;

  int tid  = threadIdx.x;
  int warp = tid >> 5, lane = tid & 31;
  int warpM = warp & 1, warpN = warp >> 1;    // 2 x 4 warp grid, 64x32 tiles

  const float* pBase = g_x + (long)bi * TS * 256;
  const float* qBase = g_x + (long)bj * TS * 256;

  uint32_t aS[3], bS[3];
  #pragma unroll
  for (int s = 0; s < 3; s++) {
    aS[s] = smem_u32(&u.mm[s][0][0]);
    bS[s] = smem_u32(&u.mm[s][1][0]);
  }

  float acc[16][4];
  #pragma unroll
  for (int i = 0; i < 16; i++)
    #pragma unroll
    for (int v = 0; v < 4; v++) acc[i][v] = 0.f;

  issue_chunk(pBase, qBase, aS[0], bS[0], 0, tid);
  issue_chunk(pBase, qBase, aS[1], bS[1], 1, tid);

  int piece = lane >> 3, pr = lane & 7;
  for (int kb = 0; kb < 16; kb++) {
    if (kb < 15) asm volatile("cp.async.wait_group 1;" ::: "memory");
    else         asm volatile("cp.async.wait_group 0;" ::: "memory");
    __syncthreads();                       // single sync per chunk
    if (kb + 2 < 16) {
      int s = (kb + 2) % 3;
      issue_chunk(pBase, qBase, aS[s], bS[s], kb + 2, tid);
    }
    uint32_t aB = aS[kb % 3], bB = bS[kb % 3];
    #pragma unroll
    for (int ks = 0; ks < 2; ks++) {          // two K=8 steps per chunk
      uint32_t aF[4][4], bF[4][2];
      #pragma unroll
      for (int mi = 0; mi < 4; mi++) {
        uint32_t addr = aB + (uint32_t)(
            (warpM*8 + mi*2 + (piece & 1))*512 + (2*ks + (piece >> 1))*128 + pr*16);
        LDMX4(aF[mi][0], aF[mi][1], aF[mi][2], aF[mi][3], addr);
      }
      #pragma unroll
      for (int np = 0; np < 2; np++) {        // n-tile pairs
        int nt = np*2 + (piece >> 1);
        uint32_t addr = bB + (uint32_t)(
            (warpN*4 + nt)*512 + (2*ks + (piece & 1))*128 + pr*16);
        LDMX4(bF[np*2][0], bF[np*2][1], bF[np*2+1][0], bF[np*2+1][1], addr);
      }
      #pragma unroll
      for (int mi = 0; mi < 4; mi++)
        #pragma unroll
        for (int ni = 0; ni < 4; ni++)
          MMA_TF32(acc[mi*4 + ni], aF[mi], bF[ni]);
    }
  }
  __syncthreads();     // all reads of stage buffers done before union reuse

  // ---- epilogue metadata + tv tiles ----
  int p0 = bi*TS, q0 = bj*TS;
  bool pS = (bi < TPD), qS = (bj < TPD);
  int type = pS ? (qS ? 0 : 1) : 2;   // 0=SS 1=ST 2=TT
  for (int r = tid; r < TS; r += 256) { u.ep.sqP[r] = g_sq[p0 + r]; u.ep.sqQ[r] = g_sq[q0 + r]; }
  if (pS) {
    for (int r = tid; r < TS; r += 256) { u.ep.cP[r] = g_cls[p0 + r]; u.ep.swP[r] = g_sw[p0 + r]; }
  } else {
    for (int idx = tid; idx < 4096; idx += 256) {
      int r = idx >> 5, c = idx & 31;
      u.ep.tv0[c*132 + r] = g_tv[(p0 - 4096)*32 + idx];
    }
  }
  if (qS) {
    for (int r = tid; r < TS; r += 256) { u.ep.cQ[r] = g_cls[q0 + r]; u.ep.swQ[r] = g_sw[q0 + r]; }
  } else {
    for (int idx = tid; idx < 4096; idx += 256) {
      int r = idx >> 5, c = idx & 31;
      u.ep.tv1[c*132 + r] = g_tv[(q0 - 4096)*32 + idx];
    }
  }
  __syncthreads();

  float neg_r = g_scalars[0];
  bool diag = (bi == bj);
  float local = 0.f;

  // Per-thread element coordinates (C-fragment mapping):
  int pv[8]; float sqp[8];
  int qv[8]; float sqq[8];
  #pragma unroll
  for (int pi = 0; pi < 8; pi++) {
    int p = warpM*64 + (pi >> 1)*16 + (pi & 1)*8 + (lane >> 2);
    pv[pi] = p; sqp[pi] = u.ep.sqP[p];
  }
  #pragma unroll
  for (int qi = 0; qi < 8; qi++) {
    int q = warpN*32 + (qi >> 1)*8 + (qi & 1) + 2*(lane & 3);
    qv[qi] = q; sqq[qi] = u.ep.sqQ[q];
  }

  #define CONTRIB(wv, dotv, pi, qi) do {                                       \
    float f_ = 2.f;                                                            \
    if (diag) { int p_ = pv[pi], q_ = qv[qi];                                  \
                f_ = (p_ > q_) ? 0.f : ((p_ == q_) ? 1.f : 2.f); }             \
    float l2_ = fmaxf(fmaf(-2.f, (dotv), sqp[pi] + sqq[qi]), 0.f);             \
    float E_  = fexp2(l2_ * neg_r);                                            \
    float E2_ = E_*E_, E4_ = E2_*E2_, E8_ = E4_*E4_, E16_ = E8_*E8_;           \
    local = fmaf(f_ * (wv), ((E_ + E2_) + (E4_ + E8_)) + E16_, local);         \
  } while (0)

  if (type == 0) {          // SS: class-equality lookup
    int cpA[8]; float swpA[8]; int cqA[8]; float swqA[8];
    #pragma unroll
    for (int pi = 0; pi < 8; pi++) { cpA[pi] = u.ep.cP[pv[pi]]; swpA[pi] = u.ep.swP[pv[pi]]; }
    #pragma unroll
    for (int qi = 0; qi < 8; qi++) { cqA[qi] = u.ep.cQ[qv[qi]]; swqA[qi] = u.ep.swQ[qv[qi]]; }
    #pragma unroll
    for (int mi = 0; mi < 4; mi++)
      #pragma unroll
      for (int ni = 0; ni < 4; ni++)
        #pragma unroll
        for (int v = 0; v < 4; v++) {
          int pi = mi*2 + (v >> 1), qi = ni*2 + (v & 1);
          float w = (cpA[pi] == cqA[qi]) ? swpA[pi]*swqA[qi] : 0.f;
          CONTRIB(w, acc[mi*4+ni][v], pi, qi);
        }
  } else if (type == 1) {   // ST: gather tvQ[class(p)][q]
    int cpA[8]; float swpA[8];
    #pragma unroll
    for (int pi = 0; pi < 8; pi++) { cpA[pi] = u.ep.cP[pv[pi]]; swpA[pi] = u.ep.swP[pv[pi]]; }
    #pragma unroll
    for (int mi = 0; mi < 4; mi++)
      #pragma unroll
      for (int ni = 0; ni < 4; ni++)
        #pragma unroll
        for (int v = 0; v < 4; v++) {
          int pi = mi*2 + (v >> 1), qi = ni*2 + (v & 1);
          float w = -swpA[pi] * u.ep.tv1[cpA[pi]*132 + qv[qi]];
          CONTRIB(w, acc[mi*4+ni][v], pi, qi);
        }
  } else {                  // TT: exact-fp32 mini-GEMM in n-quarters (W 16 regs)
    #pragma unroll
    for (int ni = 0; ni < 4; ni++) {
      float W[8][2];
      #pragma unroll
      for (int pi = 0; pi < 8; pi++) { W[pi][0] = 0.f; W[pi][1] = 0.f; }
      for (int k = 0; k < 32; k++) {
        float a[8], b0, b1;
        #pragma unroll
        for (int pi = 0; pi < 8; pi++) a[pi] = u.ep.tv0[k*132 + pv[pi]];
        b0 = u.ep.tv1[k*132 + qv[ni*2 + 0]];
        b1 = u.ep.tv1[k*132 + qv[ni*2 + 1]];
        #pragma unroll
        for (int pi = 0; pi < 8; pi++) {
          W[pi][0] = fmaf(a[pi], b0, W[pi][0]);
          W[pi][1] = fmaf(a[pi], b1, W[pi][1]);
        }
      }
      #pragma unroll
      for (int mi = 0; mi < 4; mi++)
        #pragma unroll
        for (int v = 0; v < 4; v++) {
          int pi = mi*2 + (v >> 1), qi = ni*2 + (v & 1);
          CONTRIB(W[pi][v & 1], acc[mi*4+ni][v], pi, qi);
        }
    }
  }

  #pragma unroll
  for (int o = 16; o > 0; o >>= 1) local += __shfl_down_sync(0xffffffffu, local, o);
  if (lane == 0) u.ep.red[warp] = local;
  __syncthreads();
  if (tid == 0) {
    float s = 0.f;
    #pragma unroll
    for (int wq = 0; wq < 8; wq++) s += u.ep.red[wq];
    g_partials[t0] = s;
  }
}

// ---------------------------------------------------------------------------
__global__ void k_final(float* __restrict__ out) {
  __shared__ double sd[256];
  int tid = threadIdx.x;
  double s = 0.0;
  for (int i = tid; i < NTILES; i += 256) s += (double)g_partials[i];
  sd[tid] = s; __syncthreads();
  for (int o = 128; o > 0; o >>= 1) { if (tid < o) sd[tid] += sd[tid + o]; __syncthreads(); }
  if (tid == 0) out[0] = (float)(sd[0] * (double)g_scalars[1]);
}

// ---------------------------------------------------------------------------
extern "C" void kernel_launch(void* const* d_in, const int* in_sizes, int n_in,
                              void* d_out, int out_size) {
  const float* src  = (const float*)d_in[0];
  const float* tgt  = (const float*)d_in[1];
  const void*  slab = d_in[2];
  const float* tlab = (const float*)d_in[3];

  k_pre0 <<<1, 256>>>((const int*)slab);        // launch 0
  k_cvt  <<<2048, 256>>>(src, tgt);             // launch 1
  k_stats<<<32, 128>>>(slab, tlab);             // launch 2 (+weights)
  k_fill <<<128, 256>>>(slab, tlab);            // launch 3
  k_norm <<<256, 256>>>(src, tgt);              // launch 4 (+bw)
  k_main <<<NTILES, 256>>>();                   // launch 5  <- ncu -s 5 -c 1
  k_final<<<1, 256>>>((float*)d_out);           // launch 6
}

// round 12
// speedup vs baseline: 3.5610x; 1.3574x over previous
#include <cuda_runtime.h>
#include <cuda_fp16.h>
#include <cstdint>

// ---------------------------------------------------------------------------
// LMMD loss, GB300.  Gram matrix via classic mma.sync.m16n8k16 fp16 (fp32
// accumulate; fp16 mantissa == tf32 mantissa for N(0,1) inputs, 2x MAC/instr)
// with ldmatrix fragment loads and a 3-stage cp.async pipeline.  Fused
// epilogue from register accumulators; TT weights via exact-fp32 register
// mini-GEMM.  1D triangular grid: only the 2080 upper-triangle tiles launch.
// ---------------------------------------------------------------------------

#define TPD 32
#define NT  64
#define TS  128
#define KC  32            // K-chunk (halves) per cp.async stage
#define NCHUNK 8          // 256 / 32
#define NTILES 2080       // NT*(NT+1)/2

__device__ __align__(16) __half g_xh[8192*256];  // fp16-rounded inputs
__device__ float g_sq[8192];
__device__ float g_sw[4096];
__device__ int   g_cls[4096];
__device__ float g_tv[4096*32];
__device__ float g_colsum[256];
__device__ float g_cnt_s[31], g_cnt_t[31], g_cnt_am[31];
__device__ float g_swc[32], g_tvd[32];
__device__ float g_scalars[4];      // [0]=neg_r, [1]=1/n_idx
__device__ int   g_use64;
__device__ int   g_ctr0, g_ctr1;    // last-block-done counters
__device__ float g_partials[NTILES];

static __device__ __forceinline__ uint32_t smem_u32(const void* p) {
  uint32_t a;
  asm("{ .reg .u64 t; cvta.to.shared.u64 t, %1; cvt.u32.u64 %0, t; }"
      : "=r"(a) : "l"(p));
  return a;
}

// ---------------------------------------------------------------------------
// Prologue kernels
// ---------------------------------------------------------------------------
__global__ void k_pre0(const int* __restrict__ l32) {
  __shared__ int nz;
  int t = threadIdx.x;
  if (t == 0) { nz = 0; g_ctr0 = 0; g_ctr1 = 0; }
  if (t < 256) g_colsum[t] = 0.f;
  if (t < 31) { g_cnt_s[t] = 0.f; g_cnt_t[t] = 0.f; g_cnt_am[t] = 0.f; }
  __syncthreads();
  int bad = 0;
  for (int k = t; k < 2048; k += 256)
    if (l32[2*k + 1] != 0) bad = 1;
  if (bad) atomicOr(&nz, 1);
  __syncthreads();
  if (t == 0) g_use64 = nz ? 0 : 1;
}

// Round inputs to fp16 once (rn).
__global__ void k_cvt(const float* __restrict__ s, const float* __restrict__ t) {
  int i = blockIdx.x * 256 + threadIdx.x;        // float4 index
  long base = (long)i * 4;
  const float* inp = (base < 1048576) ? (s + base) : (t + (base - 1048576));
  float4 v = *(const float4*)inp;
  uint32_t h01, h23;
  asm("cvt.rn.f16x2.f32 %0, %1, %2;" : "=r"(h01) : "f"(v.y), "f"(v.x));
  asm("cvt.rn.f16x2.f32 %0, %1, %2;" : "=r"(h23) : "f"(v.w), "f"(v.z));
  uint2 w = make_uint2(h01, h23);
  *(uint2*)&g_xh[base] = w;
}

// 32 blocks x 128 threads; the last block to finish also derives
// per-class weights + n_idx.
__global__ void k_stats(const void* __restrict__ slab,
                        const float* __restrict__ t_label) {
  __shared__ float sh_s[31], sh_t[31], sh_a[31];
  __shared__ int isLast;
  int t = threadIdx.x, lane = t & 31;
  if (t < 31) { sh_s[t] = 0.f; sh_t[t] = 0.f; sh_a[t] = 0.f; }
  __syncthreads();
  int row = blockIdx.x * 128 + t;
  bool u64 = (g_use64 != 0);
  int c = u64 ? (int)((const long long*)slab)[row] : ((const int*)slab)[row];
  atomicAdd(&sh_s[c], 1.f);
  const float* r = t_label + row * 31;
  float m = r[0]; int am = 0;
  #pragma unroll
  for (int cc = 0; cc < 31; cc++) {
    float v = r[cc];
    if (v > m) { m = v; am = cc; }
    float s = v;
    #pragma unroll
    for (int o = 16; o > 0; o >>= 1) s += __shfl_down_sync(0xffffffffu, s, o);
    if (lane == 0) atomicAdd(&sh_t[cc], s);
  }
  atomicAdd(&sh_a[am], 1.f);
  __syncthreads();
  if (t < 31) {
    atomicAdd(&g_cnt_s[t],  sh_s[t]);
    atomicAdd(&g_cnt_t[t],  sh_t[t]);
    atomicAdd(&g_cnt_am[t], sh_a[t]);
  }
  if (t == 0) {
    __threadfence();
    int o = atomicAdd(&g_ctr0, 1);
    isLast = (o == 31);
  }
  __syncthreads();
  if (isLast && t < 32) {
    __threadfence();
    float msk = 0.f, swc = 0.f, tvd = 0.f;
    if (t < 31) {
      float s = g_cnt_s[t], tc = g_cnt_t[t], a = g_cnt_am[t];
      msk = (s > 0.f && a > 0.f) ? 1.f : 0.f;
      swc = msk / ((s == 0.f) ? 100.f : s);
      tvd = msk / ((tc == 0.f) ? 100.f : tc);
    }
    g_swc[t] = swc; g_tvd[t] = tvd;
    float n = msk;
    #pragma unroll
    for (int o = 16; o > 0; o >>= 1) n += __shfl_down_sync(0xffffffffu, n, o);
    if (t == 0) g_scalars[1] = 1.f / fmaxf(n, 1.f);
  }
}

__global__ void k_fill(const void* __restrict__ slab,
                       const float* __restrict__ t_label) {
  bool u64 = (g_use64 != 0);
  int stride = gridDim.x * blockDim.x;
  for (int i = blockIdx.x * blockDim.x + threadIdx.x; i < 4096; i += stride) {
    int c = u64 ? (int)((const long long*)slab)[i] : ((const int*)slab)[i];
    g_cls[i] = c;
    g_sw[i]  = g_swc[c];
  }
  for (int idx = blockIdx.x * blockDim.x + threadIdx.x; idx < 4096*32; idx += stride) {
    int i = idx >> 5, c = idx & 31;
    g_tv[idx] = (c < 31) ? t_label[i*31 + c] * g_tvd[c] : 0.f;
  }
}

// 256 blocks x 256 threads: sq norms + colsums; last block computes bw.
__global__ void k_norm(const float* __restrict__ src, const float* __restrict__ tgt) {
  __shared__ double sd[256];
  __shared__ int isLast;
  int b = blockIdx.x, t = threadIdx.x, warp = t >> 5, lane = t & 31;
  #pragma unroll
  for (int it = 0; it < 4; it++) {
    int row = b * 32 + it * 8 + warp;
    const float* r = (row < 4096) ? src + row*256 : tgt + (row - 4096)*256;
    float s = 0.f;
    #pragma unroll
    for (int k = 0; k < 8; k++) { float v = r[lane + 32*k]; s = fmaf(v, v, s); }
    #pragma unroll
    for (int o = 16; o > 0; o >>= 1) s += __shfl_down_sync(0xffffffffu, s, o);
    if (lane == 0) g_sq[row] = s;
  }
  float cs = 0.f;
  for (int rr = 0; rr < 32; rr++) {
    int row = b * 32 + rr;
    const float* r = (row < 4096) ? src + row*256 : tgt + (row - 4096)*256;
    cs += r[t];
  }
  atomicAdd(&g_colsum[t], cs);
  if (t == 0) {
    __threadfence();
    int o = atomicAdd(&g_ctr1, 1);
    isLast = (o == 255);
  }
  __syncthreads();
  if (!isLast) return;
  __threadfence();
  double s = 0.0;
  for (int i = t; i < 8192; i += 256) s += (double)g_sq[i];
  sd[t] = s; __syncthreads();
  for (int o = 128; o > 0; o >>= 1) { if (t < o) sd[t] += sd[t + o]; __syncthreads(); }
  double S1 = sd[0];
  __syncthreads();
  double c = (double)g_colsum[t];
  sd[t] = c * c; __syncthreads();
  for (int o = 128; o > 0; o >>= 1) { if (t < o) sd[t] += sd[t + o]; __syncthreads(); }
  if (t == 0) {
    double n = 8192.0;
    double suml2 = 2.0*n*S1 - 2.0*sd[0];
    double bw = suml2 / (n*n - n);
    bw = fmax(bw, 1e-6) / 4.0;
    g_scalars[0] = (float)(-1.4426950408889634 / (16.0 * bw));
  }
}

// FMA-pipe exp2(x) for x <= 0.
__device__ __forceinline__ float fexp2(float x) {
  x = fmaxf(x, -60.f);
  float t = x + 12582912.f;                        // RN round-to-int trick
  int  ki = __float_as_int(t) - 0x4B400000;
  float r = x - (t - 12582912.f);                  // r in [-0.5, 0.5]
  float w = r * 0.69314718056f;
  float p =            1.9841270e-4f;
  p = fmaf(p, w, 1.3888889e-3f);
  p = fmaf(p, w, 8.3333333e-3f);
  p = fmaf(p, w, 4.1666667e-2f);
  p = fmaf(p, w, 1.6666667e-1f);
  p = fmaf(p, w, 0.5f);
  p = fmaf(p, w, 1.0f);
  p = fmaf(p, w, 1.0f);
  return __int_as_float(__float_as_int(p) + (ki << 23));
}

// ---------------------------------------------------------------------------
// Main tile kernel: warp-level fp16 mma.sync GEMM, 3-stage pipeline,
// fused epilogue.  SMEM = one 48KB union (stage buffers | epilogue scratch).
// ---------------------------------------------------------------------------
// Stage buffer layout per A/B: 128 rows x 32 halves (64B/row), 16B granules:
// addr(row,g) = (row>>3)*512 + g*128 + (row&7)*16.  Conflict-free ldmatrix.

union SmemU {
  __half mm[3][2][4096];    // [stage][0=A,1=B][8KB]  = 48KB exactly
  struct {
    float tv0[4224], tv1[4224];              // tv[32][132] each
    float sqP[TS], sqQ[TS], swP[TS], swQ[TS];
    float red[32];
    int   cP[TS], cQ[TS];
  } ep;
};

#define LDMX4(r0,r1,r2,r3,addr)                                                \
  asm volatile("ldmatrix.sync.aligned.m8n8.x4.shared.b16 {%0,%1,%2,%3}, [%4];" \
    : "=r"(r0), "=r"(r1), "=r"(r2), "=r"(r3) : "r"(addr))

#define MMA_F16(c, a, b)                                                       \
  asm volatile("mma.sync.aligned.m16n8k16.row.col.f32.f16.f16.f32 "            \
    "{%0,%1,%2,%3}, {%4,%5,%6,%7}, {%8,%9}, {%0,%1,%2,%3};"                    \
    : "+f"((c)[0]), "+f"((c)[1]), "+f"((c)[2]), "+f"((c)[3])                   \
    : "r"((a)[0]), "r"((a)[1]), "r"((a)[2]), "r"((a)[3]),                      \
      "r"((b)[0]), "r"((b)[1]))

static __device__ __forceinline__ void issue_chunk(
    const __half* __restrict__ pBase, const __half* __restrict__ qBase,
    uint32_t aDst, uint32_t bDst, int kb, int tid) {
  #pragma unroll
  for (int it = 0; it < 2; it++) {
    int gi  = tid * 2 + it;             // 0..511 granules
    int row = gi >> 2, g = gi & 3;
    const __half* sA = pBase + row*256 + kb*KC + g*8;
    const __half* sB = qBase + row*256 + kb*KC + g*8;
    uint32_t off = (uint32_t)((row >> 3)*512 + g*128 + (row & 7)*16);
    asm volatile("cp.async.cg.shared.global [%0], [%1], 16;"
                 :: "r"(aDst + off), "l"(sA) : "memory");
    asm volatile("cp.async.cg.shared.global [%0], [%1], 16;"
                 :: "r"(bDst + off), "l"(sB) : "memory");
  }
  asm volatile("cp.async.commit_group;" ::: "memory");
}

__global__ void __launch_bounds__(256, 2)
k_main() {
  // triangular decode: blockIdx.x -> (bi <= bj)
  int t0 = blockIdx.x;
  int bi = (int)(64.5f - sqrtf(4160.25f - 2.f*(float)t0));
  while ((bi+1)*64 - ((bi+1)*bi)/2 <= t0) bi++;
  while (bi*64 - (bi*(bi-1))/2 > t0) bi--;
  int bj = bi + (t0 - (bi*64 - (bi*(bi-1))/2));

  __shared__ __align__(16) SmemU u;

  int tid  = threadIdx.x;
  int warp = tid >> 5, lane = tid & 31;
  int warpM = warp & 1, warpN = warp >> 1;    // 2 x 4 warp grid, 64x32 tiles

  const __half* pBase = g_xh + (long)bi * TS * 256;
  const __half* qBase = g_xh + (long)bj * TS * 256;

  uint32_t aS[3], bS[3];
  #pragma unroll
  for (int s = 0; s < 3; s++) {
    aS[s] = smem_u32(&u.mm[s][0][0]);
    bS[s] = smem_u32(&u.mm[s][1][0]);
  }

  float acc[16][4];
  #pragma unroll
  for (int i = 0; i < 16; i++)
    #pragma unroll
    for (int v = 0; v < 4; v++) acc[i][v] = 0.f;

  issue_chunk(pBase, qBase, aS[0], bS[0], 0, tid);
  issue_chunk(pBase, qBase, aS[1], bS[1], 1, tid);

  int piece = lane >> 3, pr = lane & 7;
  for (int kb = 0; kb < NCHUNK; kb++) {
    if (kb < NCHUNK-1) asm volatile("cp.async.wait_group 1;" ::: "memory");
    else               asm volatile("cp.async.wait_group 0;" ::: "memory");
    __syncthreads();                       // single sync per chunk
    if (kb + 2 < NCHUNK) {
      int s = (kb + 2) % 3;
      issue_chunk(pBase, qBase, aS[s], bS[s], kb + 2, tid);
    }
    uint32_t aB = aS[kb % 3], bB = bS[kb % 3];
    #pragma unroll
    for (int ks = 0; ks < 2; ks++) {          // two K=16 steps per chunk
      uint32_t aF[4][4], bF[4][2];
      #pragma unroll
      for (int mi = 0; mi < 4; mi++) {
        uint32_t addr = aB + (uint32_t)(
            (warpM*8 + mi*2 + (piece & 1))*512 + (2*ks + (piece >> 1))*128 + pr*16);
        LDMX4(aF[mi][0], aF[mi][1], aF[mi][2], aF[mi][3], addr);
      }
      #pragma unroll
      for (int np = 0; np < 2; np++) {        // n-tile pairs
        int nt = np*2 + (piece >> 1);
        uint32_t addr = bB + (uint32_t)(
            (warpN*4 + nt)*512 + (2*ks + (piece & 1))*128 + pr*16);
        LDMX4(bF[np*2][0], bF[np*2][1], bF[np*2+1][0], bF[np*2+1][1], addr);
      }
      #pragma unroll
      for (int mi = 0; mi < 4; mi++)
        #pragma unroll
        for (int ni = 0; ni < 4; ni++)
          MMA_F16(acc[mi*4 + ni], aF[mi], bF[ni]);
    }
  }
  __syncthreads();     // all reads of stage buffers done before union reuse

  // ---- epilogue metadata + tv tiles ----
  int p0 = bi*TS, q0 = bj*TS;
  bool pS = (bi < TPD), qS = (bj < TPD);
  int type = pS ? (qS ? 0 : 1) : 2;   // 0=SS 1=ST 2=TT
  for (int r = tid; r < TS; r += 256) { u.ep.sqP[r] = g_sq[p0 + r]; u.ep.sqQ[r] = g_sq[q0 + r]; }
  if (pS) {
    for (int r = tid; r < TS; r += 256) { u.ep.cP[r] = g_cls[p0 + r]; u.ep.swP[r] = g_sw[p0 + r]; }
  } else {
    for (int idx = tid; idx < 4096; idx += 256) {
      int r = idx >> 5, c = idx & 31;
      u.ep.tv0[c*132 + r] = g_tv[(p0 - 4096)*32 + idx];
    }
  }
  if (qS) {
    for (int r = tid; r < TS; r += 256) { u.ep.cQ[r] = g_cls[q0 + r]; u.ep.swQ[r] = g_sw[q0 + r]; }
  } else {
    for (int idx = tid; idx < 4096; idx += 256) {
      int r = idx >> 5, c = idx & 31;
      u.ep.tv1[c*132 + r] = g_tv[(q0 - 4096)*32 + idx];
    }
  }
  __syncthreads();

  float neg_r = g_scalars[0];
  bool diag = (bi == bj);
  float local = 0.f;

  // Per-thread element coordinates (C-fragment mapping):
  int pv[8]; float sqp[8];
  int qv[8]; float sqq[8];
  #pragma unroll
  for (int pi = 0; pi < 8; pi++) {
    int p = warpM*64 + (pi >> 1)*16 + (pi & 1)*8 + (lane >> 2);
    pv[pi] = p; sqp[pi] = u.ep.sqP[p];
  }
  #pragma unroll
  for (int qi = 0; qi < 8; qi++) {
    int q = warpN*32 + (qi >> 1)*8 + (qi & 1) + 2*(lane & 3);
    qv[qi] = q; sqq[qi] = u.ep.sqQ[q];
  }

  #define CONTRIB(wv, dotv, pi, qi) do {                                       \
    float f_ = 2.f;                                                            \
    if (diag) { int p_ = pv[pi], q_ = qv[qi];                                  \
                f_ = (p_ > q_) ? 0.f : ((p_ == q_) ? 1.f : 2.f); }             \
    float l2_ = fmaxf(fmaf(-2.f, (dotv), sqp[pi] + sqq[qi]), 0.f);             \
    float E_  = fexp2(l2_ * neg_r);                                            \
    float E2_ = E_*E_, E4_ = E2_*E2_, E8_ = E4_*E4_, E16_ = E8_*E8_;           \
    local = fmaf(f_ * (wv), ((E_ + E2_) + (E4_ + E8_)) + E16_, local);         \
  } while (0)

  if (type == 0) {          // SS: class-equality lookup
    int cpA[8]; float swpA[8]; int cqA[8]; float swqA[8];
    #pragma unroll
    for (int pi = 0; pi < 8; pi++) { cpA[pi] = u.ep.cP[pv[pi]]; swpA[pi] = u.ep.swP[pv[pi]]; }
    #pragma unroll
    for (int qi = 0; qi < 8; qi++) { cqA[qi] = u.ep.cQ[qv[qi]]; swqA[qi] = u.ep.swQ[qv[qi]]; }
    #pragma unroll
    for (int mi = 0; mi < 4; mi++)
      #pragma unroll
      for (int ni = 0; ni < 4; ni++)
        #pragma unroll
        for (int v = 0; v < 4; v++) {
          int pi = mi*2 + (v >> 1), qi = ni*2 + (v & 1);
          float w = (cpA[pi] == cqA[qi]) ? swpA[pi]*swqA[qi] : 0.f;
          CONTRIB(w, acc[mi*4+ni][v], pi, qi);
        }
  } else if (type == 1) {   // ST: gather tvQ[class(p)][q]
    int cpA[8]; float swpA[8];
    #pragma unroll
    for (int pi = 0; pi < 8; pi++) { cpA[pi] = u.ep.cP[pv[pi]]; swpA[pi] = u.ep.swP[pv[pi]]; }
    #pragma unroll
    for (int mi = 0; mi < 4; mi++)
      #pragma unroll
      for (int ni = 0; ni < 4; ni++)
        #pragma unroll
        for (int v = 0; v < 4; v++) {
          int pi = mi*2 + (v >> 1), qi = ni*2 + (v & 1);
          float w = -swpA[pi] * u.ep.tv1[cpA[pi]*132 + qv[qi]];
          CONTRIB(w, acc[mi*4+ni][v], pi, qi);
        }
  } else {                  // TT: exact-fp32 mini-GEMM in n-quarters (W 16 regs)
    #pragma unroll
    for (int ni = 0; ni < 4; ni++) {
      float W[8][2];
      #pragma unroll
      for (int pi = 0; pi < 8; pi++) { W[pi][0] = 0.f; W[pi][1] = 0.f; }
      for (int k = 0; k < 32; k++) {
        float a[8], b0, b1;
        #pragma unroll
        for (int pi = 0; pi < 8; pi++) a[pi] = u.ep.tv0[k*132 + pv[pi]];
        b0 = u.ep.tv1[k*132 + qv[ni*2 + 0]];
        b1 = u.ep.tv1[k*132 + qv[ni*2 + 1]];
        #pragma unroll
        for (int pi = 0; pi < 8; pi++) {
          W[pi][0] = fmaf(a[pi], b0, W[pi][0]);
          W[pi][1] = fmaf(a[pi], b1, W[pi][1]);
        }
      }
      #pragma unroll
      for (int mi = 0; mi < 4; mi++)
        #pragma unroll
        for (int v = 0; v < 4; v++) {
          int pi = mi*2 + (v >> 1), qi = ni*2 + (v & 1);
          CONTRIB(W[pi][v & 1], acc[mi*4+ni][v], pi, qi);
        }
    }
  }

  #pragma unroll
  for (int o = 16; o > 0; o >>= 1) local += __shfl_down_sync(0xffffffffu, local, o);
  if (lane == 0) u.ep.red[warp] = local;
  __syncthreads();
  if (tid == 0) {
    float s = 0.f;
    #pragma unroll
    for (int wq = 0; wq < 8; wq++) s += u.ep.red[wq];
    g_partials[t0] = s;
  }
}

// ---------------------------------------------------------------------------
__global__ void k_final(float* __restrict__ out) {
  __shared__ double sd[256];
  int tid = threadIdx.x;
  double s = 0.0;
  for (int i = tid; i < NTILES; i += 256) s += (double)g_partials[i];
  sd[tid] = s; __syncthreads();
  for (int o = 128; o > 0; o >>= 1) { if (tid < o) sd[tid] += sd[tid + o]; __syncthreads(); }
  if (tid == 0) out[0] = (float)(sd[0] * (double)g_scalars[1]);
}

// ---------------------------------------------------------------------------
extern "C" void kernel_launch(void* const* d_in, const int* in_sizes, int n_in,
                              void* d_out, int out_size) {
  const float* src  = (const float*)d_in[0];
  const float* tgt  = (const float*)d_in[1];
  const void*  slab = d_in[2];
  const float* tlab = (const float*)d_in[3];

  k_pre0 <<<1, 256>>>((const int*)slab);        // launch 0
  k_cvt  <<<2048, 256>>>(src, tgt);             // launch 1
  k_stats<<<32, 128>>>(slab, tlab);             // launch 2 (+weights)
  k_fill <<<128, 256>>>(slab, tlab);            // launch 3
  k_norm <<<256, 256>>>(src, tgt);              // launch 4 (+bw)
  k_main <<<NTILES, 256>>>();                   // launch 5
  k_final<<<1, 256>>>((float*)d_out);           // launch 6
}

// round 14
// speedup vs baseline: 4.3059x; 1.2092x over previous
#include <cuda_runtime.h>
#include <cuda_fp16.h>
#include <cstdint>

// ---------------------------------------------------------------------------
// LMMD loss, GB300.  Gram matrix via classic mma.sync.m16n8k16 fp16 (fp32
// accumulate) with ldmatrix fragment loads and a 3-stage cp.async pipeline.
// Fused epilogue from register accumulators.  TT weights now ALSO computed
// on tensor cores (K=32 fp16 MMA over scaled tv tiles) instead of a per-
// thread FFMA/LDS mini-GEMM.  5 launches total.
// ---------------------------------------------------------------------------

#define TPD 32
#define NT  64
#define TS  128
#define KC  32            // K-chunk (halves) per cp.async stage
#define NCHUNK 8          // 256 / 32
#define NTILES 2080       // NT*(NT+1)/2
#define TVSC  512.0f
#define TVSC_INV2 (1.0f/(512.0f*512.0f))

__device__ __align__(16) __half g_xh[8192*256];  // fp16-rounded inputs
__device__ __align__(16) __half g_tvh[4096*32];  // fp16 tv * 512 (TT weights)
__device__ float g_sq[8192];
__device__ float g_sw[4096];
__device__ int   g_cls[4096];
__device__ float g_tv[4096*32];
__device__ float g_colsum[256];
__device__ float g_cnt_s[31], g_cnt_t[31], g_cnt_am[31];
__device__ float g_swc[32], g_tvd[32];
__device__ float g_scalars[4];      // [0]=neg_r, [1]=1/n_idx
__device__ int   g_use64;
__device__ int   g_ctr0, g_ctr1;    // last-block-done counters
__device__ float g_partials[NTILES];

static __device__ __forceinline__ uint32_t smem_u32(const void* p) {
  uint32_t a;
  asm("{ .reg .u64 t; cvta.to.shared.u64 t, %1; cvt.u32.u64 %0, t; }"
      : "=r"(a) : "l"(p));
  return a;
}

// ---------------------------------------------------------------------------
// Launch 0: fp16 convert (blocks 0..2047) + label-width detect / counter
// zeroing (block 2048).
// ---------------------------------------------------------------------------
__global__ void k_pre(const float* __restrict__ s, const float* __restrict__ t,
                      const int* __restrict__ l32) {
  if (blockIdx.x == 2048) {
    __shared__ int nz;
    int tt = threadIdx.x;
    if (tt == 0) { nz = 0; g_ctr0 = 0; g_ctr1 = 0; }
    if (tt < 256) g_colsum[tt] = 0.f;
    if (tt < 31) { g_cnt_s[tt] = 0.f; g_cnt_t[tt] = 0.f; g_cnt_am[tt] = 0.f; }
    __syncthreads();
    int bad = 0;
    for (int k = tt; k < 2048; k += 256)
      if (l32[2*k + 1] != 0) bad = 1;
    if (bad) atomicOr(&nz, 1);
    __syncthreads();
    if (tt == 0) g_use64 = nz ? 0 : 1;
    return;
  }
  int i = blockIdx.x * 256 + threadIdx.x;        // float4 index
  long base = (long)i * 4;
  const float* inp = (base < 1048576) ? (s + base) : (t + (base - 1048576));
  float4 v = *(const float4*)inp;
  uint32_t h01, h23;
  asm("cvt.rn.f16x2.f32 %0, %1, %2;" : "=r"(h01) : "f"(v.y), "f"(v.x));
  asm("cvt.rn.f16x2.f32 %0, %1, %2;" : "=r"(h23) : "f"(v.w), "f"(v.z));
  uint2 w = make_uint2(h01, h23);
  *(uint2*)&g_xh[base] = w;
}

// ---------------------------------------------------------------------------
// Launch 1: label statistics; last block derives per-class weights + n_idx.
// ---------------------------------------------------------------------------
__global__ void k_stats(const void* __restrict__ slab,
                        const float* __restrict__ t_label) {
  __shared__ float sh_s[31], sh_t[31], sh_a[31];
  __shared__ int isLast;
  int t = threadIdx.x, lane = t & 31;
  if (t < 31) { sh_s[t] = 0.f; sh_t[t] = 0.f; sh_a[t] = 0.f; }
  __syncthreads();
  int row = blockIdx.x * 128 + t;
  bool u64 = (g_use64 != 0);
  int c = u64 ? (int)((const long long*)slab)[row] : ((const int*)slab)[row];
  atomicAdd(&sh_s[c], 1.f);
  const float* r = t_label + row * 31;
  float m = r[0]; int am = 0;
  #pragma unroll
  for (int cc = 0; cc < 31; cc++) {
    float v = r[cc];
    if (v > m) { m = v; am = cc; }
    float s = v;
    #pragma unroll
    for (int o = 16; o > 0; o >>= 1) s += __shfl_down_sync(0xffffffffu, s, o);
    if (lane == 0) atomicAdd(&sh_t[cc], s);
  }
  atomicAdd(&sh_a[am], 1.f);
  __syncthreads();
  if (t < 31) {
    atomicAdd(&g_cnt_s[t],  sh_s[t]);
    atomicAdd(&g_cnt_t[t],  sh_t[t]);
    atomicAdd(&g_cnt_am[t], sh_a[t]);
  }
  if (t == 0) {
    __threadfence();
    int o = atomicAdd(&g_ctr0, 1);
    isLast = (o == 31);
  }
  __syncthreads();
  if (isLast && t < 32) {
    __threadfence();
    float msk = 0.f, swc = 0.f, tvd = 0.f;
    if (t < 31) {
      float s = g_cnt_s[t], tc = g_cnt_t[t], a = g_cnt_am[t];
      msk = (s > 0.f && a > 0.f) ? 1.f : 0.f;
      swc = msk / ((s == 0.f) ? 100.f : s);
      tvd = msk / ((tc == 0.f) ? 100.f : tc);
    }
    g_swc[t] = swc; g_tvd[t] = tvd;
    float n = msk;
    #pragma unroll
    for (int o = 16; o > 0; o >>= 1) n += __shfl_down_sync(0xffffffffu, n, o);
    if (t == 0) g_scalars[1] = 1.f / fmaxf(n, 1.f);
  }
}

// ---------------------------------------------------------------------------
// Launch 2: blocks 0..255 = sq norms + colsums (+bw in last norm block);
//           blocks 256..383 = per-row weight / tv / tvh fill.
// ---------------------------------------------------------------------------
__global__ void k_fillnorm(const float* __restrict__ src,
                           const float* __restrict__ tgt,
                           const void* __restrict__ slab,
                           const float* __restrict__ t_label) {
  __shared__ double sd[256];
  __shared__ int isLast;
  int b = blockIdx.x, t = threadIdx.x;
  if (b >= 256) {
    int bb = b - 256;
    bool u64 = (g_use64 != 0);
    int stride = 128 * 256;
    for (int i = bb * 256 + t; i < 4096; i += stride) {
      int c = u64 ? (int)((const long long*)slab)[i] : ((const int*)slab)[i];
      g_cls[i] = c;
      g_sw[i]  = g_swc[c];
    }
    for (int idx = bb * 256 + t; idx < 4096*32; idx += stride) {
      int i = idx >> 5, c = idx & 31;
      float v = (c < 31) ? t_label[i*31 + c] * g_tvd[c] : 0.f;
      g_tv[idx]  = v;
      g_tvh[idx] = __float2half(v * TVSC);
    }
    return;
  }
  int warp = t >> 5, lane = t & 31;
  #pragma unroll
  for (int it = 0; it < 4; it++) {
    int row = b * 32 + it * 8 + warp;
    const float* r = (row < 4096) ? src + row*256 : tgt + (row - 4096)*256;
    float s = 0.f;
    #pragma unroll
    for (int k = 0; k < 8; k++) { float v = r[lane + 32*k]; s = fmaf(v, v, s); }
    #pragma unroll
    for (int o = 16; o > 0; o >>= 1) s += __shfl_down_sync(0xffffffffu, s, o);
    if (lane == 0) g_sq[row] = s;
  }
  float cs = 0.f;
  for (int rr = 0; rr < 32; rr++) {
    int row = b * 32 + rr;
    const float* r = (row < 4096) ? src + row*256 : tgt + (row - 4096)*256;
    cs += r[t];
  }
  atomicAdd(&g_colsum[t], cs);
  if (t == 0) {
    __threadfence();
    int o = atomicAdd(&g_ctr1, 1);
    isLast = (o == 255);
  }
  __syncthreads();
  if (!isLast) return;
  __threadfence();
  double s = 0.0;
  for (int i = t; i < 8192; i += 256) s += (double)g_sq[i];
  sd[t] = s; __syncthreads();
  for (int o = 128; o > 0; o >>= 1) { if (t < o) sd[t] += sd[t + o]; __syncthreads(); }
  double S1 = sd[0];
  __syncthreads();
  double c = (double)g_colsum[t];
  sd[t] = c * c; __syncthreads();
  for (int o = 128; o > 0; o >>= 1) { if (t < o) sd[t] += sd[t + o]; __syncthreads(); }
  if (t == 0) {
    double n = 8192.0;
    double suml2 = 2.0*n*S1 - 2.0*sd[0];
    double bw = suml2 / (n*n - n);
    bw = fmax(bw, 1e-6) / 4.0;
    g_scalars[0] = (float)(-1.4426950408889634 / (16.0 * bw));
  }
}

// FMA-pipe exp2(x) for x <= 0.
__device__ __forceinline__ float fexp2(float x) {
  x = fmaxf(x, -60.f);
  float t = x + 12582912.f;                        // RN round-to-int trick
  int  ki = __float_as_int(t) - 0x4B400000;
  float r = x - (t - 12582912.f);                  // r in [-0.5, 0.5]
  float w = r * 0.69314718056f;
  float p =            1.9841270e-4f;
  p = fmaf(p, w, 1.3888889e-3f);
  p = fmaf(p, w, 8.3333333e-3f);
  p = fmaf(p, w, 4.1666667e-2f);
  p = fmaf(p, w, 1.6666667e-1f);
  p = fmaf(p, w, 0.5f);
  p = fmaf(p, w, 1.0f);
  p = fmaf(p, w, 1.0f);
  return __int_as_float(__float_as_int(p) + (ki << 23));
}

// ---------------------------------------------------------------------------
// Main tile kernel.
// Stage buffer layout per A/B: 128 rows x 32 halves (64B/row), 16B granules:
// addr(row,g) = (row>>3)*512 + g*128 + (row&7)*16.  Conflict-free ldmatrix.
// ---------------------------------------------------------------------------
union SmemU {
  __half mm[3][2][4096];    // [stage][0=A,1=B][8KB]  = 48KB exactly
  struct {
    float tv0[4224], tv1[4224];              // fp32 tv (ST gather path only)
    float sqP[TS], sqQ[TS], swP[TS], swQ[TS];
    float red[32];
    int   cP[TS], cQ[TS];
  } ep;
};

#define LDMX4(r0,r1,r2,r3,addr)                                                \
  asm volatile("ldmatrix.sync.aligned.m8n8.x4.shared.b16 {%0,%1,%2,%3}, [%4];" \
    : "=r"(r0), "=r"(r1), "=r"(r2), "=r"(r3) : "r"(addr))

#define MMA_F16(c, a, b)                                                       \
  asm volatile("mma.sync.aligned.m16n8k16.row.col.f32.f16.f16.f32 "            \
    "{%0,%1,%2,%3}, {%4,%5,%6,%7}, {%8,%9}, {%0,%1,%2,%3};"                    \
    : "+f"((c)[0]), "+f"((c)[1]), "+f"((c)[2]), "+f"((c)[3])                   \
    : "r"((a)[0]), "r"((a)[1]), "r"((a)[2]), "r"((a)[3]),                      \
      "r"((b)[0]), "r"((b)[1]))

static __device__ __forceinline__ void issue_chunk(
    const __half* __restrict__ pBase, const __half* __restrict__ qBase,
    uint32_t aDst, uint32_t bDst, int kb, int tid) {
  #pragma unroll
  for (int it = 0; it < 2; it++) {
    int gi  = tid * 2 + it;             // 0..511 granules
    int row = gi >> 2, g = gi & 3;
    const __half* sA = pBase + row*256 + kb*KC + g*8;
    const __half* sB = qBase + row*256 + kb*KC + g*8;
    uint32_t off = (uint32_t)((row >> 3)*512 + g*128 + (row & 7)*16);
    asm volatile("cp.async.cg.shared.global [%0], [%1], 16;"
                 :: "r"(aDst + off), "l"(sA) : "memory");
    asm volatile("cp.async.cg.shared.global [%0], [%1], 16;"
                 :: "r"(bDst + off), "l"(sB) : "memory");
  }
  asm volatile("cp.async.commit_group;" ::: "memory");
}

__global__ void __launch_bounds__(256, 2)
k_main() {
  // triangular decode: blockIdx.x -> (bi <= bj)
  int t0 = blockIdx.x;
  int bi = (int)(64.5f - sqrtf(4160.25f - 2.f*(float)t0));
  while ((bi+1)*64 - ((bi+1)*bi)/2 <= t0) bi++;
  while (bi*64 - (bi*(bi-1))/2 > t0) bi--;
  int bj = bi + (t0 - (bi*64 - (bi*(bi-1))/2));

  __shared__ __align__(16) SmemU u;

  int tid  = threadIdx.x;
  int warp = tid >> 5, lane = tid & 31;
  int warpM = warp & 1, warpN = warp >> 1;    // 2 x 4 warp grid, 64x32 tiles

  const __half* pBase = g_xh + (long)bi * TS * 256;
  const __half* qBase = g_xh + (long)bj * TS * 256;

  uint32_t aS[3], bS[3];
  #pragma unroll
  for (int s = 0; s < 3; s++) {
    aS[s] = smem_u32(&u.mm[s][0][0]);
    bS[s] = smem_u32(&u.mm[s][1][0]);
  }

  float acc[16][4];
  #pragma unroll
  for (int i = 0; i < 16; i++)
    #pragma unroll
    for (int v = 0; v < 4; v++) acc[i][v] = 0.f;

  issue_chunk(pBase, qBase, aS[0], bS[0], 0, tid);
  issue_chunk(pBase, qBase, aS[1], bS[1], 1, tid);

  int piece = lane >> 3, pr = lane & 7;
  for (int kb = 0; kb < NCHUNK; kb++) {
    if (kb < NCHUNK-1) asm volatile("cp.async.wait_group 1;" ::: "memory");
    else               asm volatile("cp.async.wait_group 0;" ::: "memory");
    __syncthreads();                       // single sync per chunk
    if (kb + 2 < NCHUNK) {
      int s = (kb + 2) % 3;
      issue_chunk(pBase, qBase, aS[s], bS[s], kb + 2, tid);
    }
    uint32_t aB = aS[kb % 3], bB = bS[kb % 3];
    #pragma unroll
    for (int ks = 0; ks < 2; ks++) {          // two K=16 steps per chunk
      uint32_t aF[4][4], bF[4][2];
      #pragma unroll
      for (int mi = 0; mi < 4; mi++) {
        uint32_t addr = aB + (uint32_t)(
            (warpM*8 + mi*2 + (piece & 1))*512 + (2*ks + (piece >> 1))*128 + pr*16);
        LDMX4(aF[mi][0], aF[mi][1], aF[mi][2], aF[mi][3], addr);
      }
      #pragma unroll
      for (int np = 0; np < 2; np++) {        // n-tile pairs
        int nt = np*2 + (piece >> 1);
        uint32_t addr = bB + (uint32_t)(
            (warpN*4 + nt)*512 + (2*ks + (piece & 1))*128 + pr*16);
        LDMX4(bF[np*2][0], bF[np*2][1], bF[np*2+1][0], bF[np*2+1][1], addr);
      }
      #pragma unroll
      for (int mi = 0; mi < 4; mi++)
        #pragma unroll
        for (int ni = 0; ni < 4; ni++)
          MMA_F16(acc[mi*4 + ni], aF[mi], bF[ni]);
    }
  }
  __syncthreads();     // all reads of stage buffers done before reuse

  // ---- epilogue metadata ----
  int p0 = bi*TS, q0 = bj*TS;
  bool pS = (bi < TPD), qS = (bj < TPD);
  int type = pS ? (qS ? 0 : 1) : 2;   // 0=SS 1=ST 2=TT
  for (int r = tid; r < TS; r += 256) { u.ep.sqP[r] = g_sq[p0 + r]; u.ep.sqQ[r] = g_sq[q0 + r]; }
  if (type == 0) {
    for (int r = tid; r < TS; r += 256) {
      u.ep.cP[r] = g_cls[p0 + r]; u.ep.swP[r] = g_sw[p0 + r];
      u.ep.cQ[r] = g_cls[q0 + r]; u.ep.swQ[r] = g_sw[q0 + r];
    }
  } else if (type == 1) {
    for (int r = tid; r < TS; r += 256) { u.ep.cP[r] = g_cls[p0 + r]; u.ep.swP[r] = g_sw[p0 + r]; }
    for (int idx = tid; idx < 4096; idx += 256) {
      int r = idx >> 5, c = idx & 31;
      u.ep.tv1[c*132 + r] = g_tv[(q0 - 4096)*32 + idx];
    }
  }
  __syncthreads();

  float neg_r = g_scalars[0];
  bool diag = (bi == bj);
  float local = 0.f;

  // Per-thread element coordinates (C-fragment mapping):
  int pv[8]; float sqp[8];
  int qv[8]; float sqq[8];
  #pragma unroll
  for (int pi = 0; pi < 8; pi++) {
    int p = warpM*64 + (pi >> 1)*16 + (pi & 1)*8 + (lane >> 2);
    pv[pi] = p; sqp[pi] = u.ep.sqP[p];
  }
  #pragma unroll
  for (int qi = 0; qi < 8; qi++) {
    int q = warpN*32 + (qi >> 1)*8 + (qi & 1) + 2*(lane & 3);
    qv[qi] = q; sqq[qi] = u.ep.sqQ[q];
  }

  #define CONTRIB(wv, dotv, pi, qi) do {                                       \
    float f_ = 2.f;                                                            \
    if (diag) { int p_ = pv[pi], q_ = qv[qi];                                  \
                f_ = (p_ > q_) ? 0.f : ((p_ == q_) ? 1.f : 2.f); }             \
    float l2_ = fmaxf(fmaf(-2.f, (dotv), sqp[pi] + sqq[qi]), 0.f);             \
    float E_  = fexp2(l2_ * neg_r);                                            \
    float E2_ = E_*E_, E4_ = E2_*E2_, E8_ = E4_*E4_, E16_ = E8_*E8_;           \
    local = fmaf(f_ * (wv), ((E_ + E2_) + (E4_ + E8_)) + E16_, local);         \
  } while (0)

  if (type == 0) {          // SS: class-equality lookup
    int cpA[8]; float swpA[8]; int cqA[8]; float swqA[8];
    #pragma unroll
    for (int pi = 0; pi < 8; pi++) { cpA[pi] = u.ep.cP[pv[pi]]; swpA[pi] = u.ep.swP[pv[pi]]; }
    #pragma unroll
    for (int qi = 0; qi < 8; qi++) { cqA[qi] = u.ep.cQ[qv[qi]]; swqA[qi] = u.ep.swQ[qv[qi]]; }
    #pragma unroll
    for (int mi = 0; mi < 4; mi++)
      #pragma unroll
      for (int ni = 0; ni < 4; ni++)
        #pragma unroll
        for (int v = 0; v < 4; v++) {
          int pi = mi*2 + (v >> 1), qi = ni*2 + (v & 1);
          float w = (cpA[pi] == cqA[qi]) ? swpA[pi]*swqA[qi] : 0.f;
          CONTRIB(w, acc[mi*4+ni][v], pi, qi);
        }
  } else if (type == 1) {   // ST: gather tvQ[class(p)][q]
    int cpA[8]; float swpA[8];
    #pragma unroll
    for (int pi = 0; pi < 8; pi++) { cpA[pi] = u.ep.cP[pv[pi]]; swpA[pi] = u.ep.swP[pv[pi]]; }
    #pragma unroll
    for (int mi = 0; mi < 4; mi++)
      #pragma unroll
      for (int ni = 0; ni < 4; ni++)
        #pragma unroll
        for (int v = 0; v < 4; v++) {
          int pi = mi*2 + (v >> 1), qi = ni*2 + (v & 1);
          float w = -swpA[pi] * u.ep.tv1[cpA[pi]*132 + qv[qi]];
          CONTRIB(w, acc[mi*4+ni][v], pi, qi);
        }
  } else {                  // TT: W = TvP * TvQ^T on tensor cores (K=32 fp16)
    const __half* tp = g_tvh + (long)(p0 - 4096) * 32;
    const __half* tq = g_tvh + (long)(q0 - 4096) * 32;
    #pragma unroll
    for (int it = 0; it < 2; it++) {
      int gi = tid*2 + it;
      int row = gi >> 2, g = gi & 3;
      uint32_t off = (uint32_t)((row >> 3)*512 + g*128 + (row & 7)*16);
      asm volatile("cp.async.cg.shared.global [%0], [%1], 16;"
                   :: "r"(aS[0] + off), "l"(tp + row*32 + g*8) : "memory");
      asm volatile("cp.async.cg.shared.global [%0], [%1], 16;"
                   :: "r"(bS[0] + off), "l"(tq + row*32 + g*8) : "memory");
    }
    asm volatile("cp.async.commit_group;" ::: "memory");
    asm volatile("cp.async.wait_group 0;" ::: "memory");
    __syncthreads();
    #pragma unroll
    for (int np = 0; np < 2; np++) {
      float W[4][2][4];
      #pragma unroll
      for (int mi = 0; mi < 4; mi++)
        #pragma unroll
        for (int nl = 0; nl < 2; nl++)
          #pragma unroll
          for (int v = 0; v < 4; v++) W[mi][nl][v] = 0.f;
      #pragma unroll
      for (int ks = 0; ks < 2; ks++) {
        uint32_t aF[4][4], bF[2][2];
        #pragma unroll
        for (int mi = 0; mi < 4; mi++) {
          uint32_t addr = aS[0] + (uint32_t)(
              (warpM*8 + mi*2 + (piece & 1))*512 + (2*ks + (piece >> 1))*128 + pr*16);
          LDMX4(aF[mi][0], aF[mi][1], aF[mi][2], aF[mi][3], addr);
        }
        {
          int nt = np*2 + (piece >> 1);
          uint32_t addr = bS[0] + (uint32_t)(
              (warpN*4 + nt)*512 + (2*ks + (piece & 1))*128 + pr*16);
          LDMX4(bF[0][0], bF[0][1], bF[1][0], bF[1][1], addr);
        }
        #pragma unroll
        for (int mi = 0; mi < 4; mi++)
          #pragma unroll
          for (int nl = 0; nl < 2; nl++)
            MMA_F16(W[mi][nl], aF[mi], bF[nl]);
      }
      #pragma unroll
      for (int nl = 0; nl < 2; nl++) {
        int ni = np*2 + nl;
        #pragma unroll
        for (int mi = 0; mi < 4; mi++)
          #pragma unroll
          for (int v = 0; v < 4; v++) {
            int pi = mi*2 + (v >> 1), qi = ni*2 + (v & 1);
            CONTRIB(W[mi][nl][v] * TVSC_INV2, acc[mi*4+ni][v], pi, qi);
          }
      }
    }
  }

  #pragma unroll
  for (int o = 16; o > 0; o >>= 1) local += __shfl_down_sync(0xffffffffu, local, o);
  if (lane == 0) u.ep.red[warp] = local;
  __syncthreads();
  if (tid == 0) {
    float s = 0.f;
    #pragma unroll
    for (int wq = 0; wq < 8; wq++) s += u.ep.red[wq];
    g_partials[t0] = s;
  }
}

// ---------------------------------------------------------------------------
__global__ void k_final(float* __restrict__ out) {
  __shared__ double sd[256];
  int tid = threadIdx.x;
  double s = 0.0;
  for (int i = tid; i < NTILES; i += 256) s += (double)g_partials[i];
  sd[tid] = s; __syncthreads();
  for (int o = 128; o > 0; o >>= 1) { if (tid < o) sd[tid] += sd[tid + o]; __syncthreads(); }
  if (tid == 0) out[0] = (float)(sd[0] * (double)g_scalars[1]);
}

// ---------------------------------------------------------------------------
extern "C" void kernel_launch(void* const* d_in, const int* in_sizes, int n_in,
                              void* d_out, int out_size) {
  const float* src  = (const float*)d_in[0];
  const float* tgt  = (const float*)d_in[1];
  const void*  slab = d_in[2];
  const float* tlab = (const float*)d_in[3];

  k_pre     <<<2049, 256>>>(src, tgt, (const int*)slab);   // launch 0
  k_stats   <<<32, 128>>>(slab, tlab);                     // launch 1
  k_fillnorm<<<384, 256>>>(src, tgt, slab, tlab);          // launch 2
  k_main    <<<NTILES, 256>>>();                           // launch 3
  k_final   <<<1, 256>>>((float*)d_out);                   // launch 4
}